// round 7
// baseline (speedup 1.0000x reference)
#include <cuda_runtime.h>

#define BB 64
#define VV 2000
#define DD 16
#define CI 64
#define CO 64
#define OPS 65   // padded operand row stride: kills 2-way LDS bank conflicts

// ---------------- scratch (device globals, no allocation) ----------------
__device__ float g_partG[32 * 512];
__device__ float g_Zre[BB * DD * CI];
__device__ float g_Zim[BB * DD * CI];
__device__ float g_yre[(size_t)BB * VV * CI];
__device__ float g_yim[(size_t)BB * VV * CI];
__device__ float4 g_AC4[(size_t)VV * CI * CO];   // (Ar, Ai, Cr, Ci)

// ================ K1: gram_partial (blocks 0-31) + z (blocks 32-287) ================
__global__ void __launch_bounds__(256) k1_gram_z(const float* __restrict__ x,
                                                 const float* __restrict__ ner,
                                                 const float* __restrict__ nei) {
    __shared__ float sm[4608];
    if (blockIdx.x < 32) {
        float* sr = sm;
        float* si = sm + 1008;
        int blk = blockIdx.x;
        int v0 = blk * 63;
        int cnt = min(63, VV - v0);
        for (int t = threadIdx.x; t < cnt * 16; t += 256) {
            sr[t] = ner[v0 * 16 + t];
            si[t] = nei[v0 * 16 + t];
        }
        __syncthreads();
        int d = threadIdx.x >> 4, e = threadIdx.x & 15;
        float ar = 0.f, ai = 0.f;
        for (int vv = 0; vv < cnt; vv++) {
            float a = sr[vv * 16 + d], b = si[vv * 16 + d];
            float c = sr[vv * 16 + e], dd = si[vv * 16 + e];
            ar += a * c + b * dd;
            ai += a * dd - b * c;
        }
        g_partG[blk * 512 + threadIdx.x * 2]     = ar;
        g_partG[blk * 512 + threadIdx.x * 2 + 1] = ai;
    } else {
        // z: Z[b,d,i] = sum_v conj(ne[v,d]) * x[b,v,i]
        float* xs = sm;
        float* nr = sm + 4096;
        float* ni = sm + 4352;
        int bx = blockIdx.x - 32;
        int b = bx >> 2;
        int d0 = (bx & 3) * 4;
        int i = threadIdx.x & 63;
        int dl = threadIdx.x >> 6;
        float ar = 0.f, ai = 0.f;
        for (int v0 = 0; v0 < VV; v0 += 64) {
            int cnt = min(64, VV - v0);
            __syncthreads();
            for (int t = threadIdx.x; t < cnt * 64; t += 256)
                xs[t] = x[(size_t)b * VV * 64 + (size_t)v0 * 64 + t];
            for (int t = threadIdx.x; t < cnt * 4; t += 256) {
                int vv = t >> 2, dd = t & 3;
                nr[t] = ner[(v0 + vv) * 16 + d0 + dd];
                ni[t] = nei[(v0 + vv) * 16 + d0 + dd];
            }
            __syncthreads();
            for (int vv = 0; vv < cnt; vv++) {
                float xv = xs[vv * 64 + i];
                ar += nr[vv * 4 + dl] * xv;
                ai -= ni[vv * 4 + dl] * xv;
            }
        }
        g_Zre[(b * 16 + d0 + dl) * 64 + i] = ar;
        g_Zim[(b * 16 + d0 + dl) * 64 + i] = ai;
    }
}

// ================ K2: y (pure) ================
__global__ void __launch_bounds__(256) y_kernel(const float* __restrict__ ner,
                                                const float* __restrict__ nei) {
    __shared__ float sm[4096];
    float* Zr = sm;
    float* Zi = sm + 1024;
    float* nr = sm + 2048;
    float* ni = sm + 3072;
    int b = blockIdx.x >> 5;
    int v0 = (blockIdx.x & 31) * 64;
    int vcnt = min(64, VV - v0);
    for (int t = threadIdx.x; t < 1024; t += 256) {
        Zr[t] = g_Zre[b * 1024 + t];
        Zi[t] = g_Zim[b * 1024 + t];
    }
    for (int t = threadIdx.x; t < vcnt * 16; t += 256) {
        nr[t] = ner[v0 * 16 + t];
        ni[t] = nei[v0 * 16 + t];
    }
    __syncthreads();
    int i = threadIdx.x & 63;
    int vb = threadIdx.x >> 6;
    float zr[16], zi[16];
#pragma unroll
    for (int d = 0; d < 16; d++) { zr[d] = Zr[d * 64 + i]; zi[d] = Zi[d * 64 + i]; }
    for (int vl = vb; vl < vcnt; vl += 4) {
        float yr = 0.f, yi = 0.f;
#pragma unroll
        for (int d = 0; d < 16; d++) {
            float a = nr[vl * 16 + d], c = ni[vl * 16 + d];
            yr += a * zr[d] - c * zi[d];
            yi += a * zi[d] + c * zr[d];
        }
        size_t o = (size_t)b * VV * 64 + (size_t)(v0 + vl) * 64 + i;
        g_yre[o] = yr;
        g_yim[o] = yi;
    }
}

// ================ K3: wcomb (inline gram reduce + float4 output) ================
__global__ void __launch_bounds__(256) wcomb_kernel(const float* __restrict__ ner,
                                                    const float* __restrict__ nei,
                                                    const float* __restrict__ wr,
                                                    const float* __restrict__ wi) {
    __shared__ float red[256];
    __shared__ float s_inv;
    __shared__ float nr[100 * 16], ni[100 * 16];
    int t = threadIdx.x;
    // inline gram reduce (redundant per block, reads L2-resident partials)
    {
        float gr = 0.f, gi = 0.f;
        for (int blk = 0; blk < 32; blk++) {
            gr += g_partG[blk * 512 + t * 2];
            gi += g_partG[blk * 512 + t * 2 + 1];
        }
        red[t] = gr * gr + gi * gi;
        __syncthreads();
        for (int s = 128; s > 0; s >>= 1) {
            if (t < s) red[t] += red[t + s];
            __syncthreads();
        }
        if (t == 0) s_inv = rsqrtf(red[0]);
    }

    int io = blockIdx.x * 256 + t;
    int vstart = blockIdx.y * 100;
    for (int n = t; n < 100 * 16; n += 256) {
        nr[n] = ner[vstart * 16 + n];
        ni[n] = nei[vstart * 16 + n];
    }
    __syncthreads();
    float s = s_inv;
    float P0r[16], P0i[16], P1r[16], P1i[16];
#pragma unroll
    for (int d = 0; d < 16; d++) {
        float r0 = wr[(d * 3 + 0) * 4096 + io];
        float r1 = wr[(d * 3 + 1) * 4096 + io];
        float r2 = wr[(d * 3 + 2) * 4096 + io];
        float i0 = wi[(d * 3 + 0) * 4096 + io];
        float i1 = wi[(d * 3 + 1) * 4096 + io];
        float i2 = wi[(d * 3 + 2) * 4096 + io];
        P0r[d] = r0 - r2;
        P0i[d] = i0 - i2;
        P1r[d] = (r1 + 2.f * r2) * s;
        P1i[d] = (i1 + 2.f * i2) * s;
    }
    for (int vl = 0; vl < 100; vl++) {
        float Ar = 0.f, Ai = 0.f, Cr = 0.f, Ci = 0.f;
#pragma unroll
        for (int d = 0; d < 16; d++) {
            float a = nr[vl * 16 + d], b = ni[vl * 16 + d];
            Ar += a * P0r[d] - b * P0i[d];
            Ai += a * P0i[d] + b * P0r[d];
            Cr += a * P1r[d] - b * P1i[d];
            Ci += a * P1i[d] + b * P1r[d];
        }
        g_AC4[(size_t)(vstart + vl) * 4096 + io] = make_float4(Ar, Ai, Cr, Ci);
    }
}

// ================ K4: final per-node GEMM ================
__global__ void __launch_bounds__(256) out_kernel(const float* __restrict__ x,
                                                  const float* __restrict__ ner,
                                                  const float* __restrict__ nei,
                                                  const float* __restrict__ bre,
                                                  const float* __restrict__ bim,
                                                  float* __restrict__ out) {
    extern __shared__ float sm[];
    float* Ar = sm;                      // 4096 (stride 64, LDS.128 reads)
    float* Ai = sm + 4096;
    float* Cr = sm + 8192;
    float* Ci = sm + 12288;
    float* xs = sm + 16384;              // [b][OPS=65] padded
    float* yr = xs + 64 * OPS;
    float* yi = yr + 64 * OPS;
    float* br = yi + 64 * OPS;           // 64
    float* bi = br + 64;

    int v = blockIdx.x;
    size_t vo = (size_t)v * 4096;
    // de-interleave coefficients: LDG.128 -> 4x STS.32 (conflict-free)
    for (int t = threadIdx.x; t < 4096; t += 256) {
        float4 c = g_AC4[vo + t];
        Ar[t] = c.x; Ai[t] = c.y; Cr[t] = c.z; Ci[t] = c.w;
        int b = t >> 6, i = t & 63;
        size_t xoff = (size_t)b * (VV * 64) + (size_t)v * 64 + i;
        xs[b * OPS + i] = x[xoff];
        yr[b * OPS + i] = g_yre[xoff];
        yi[b * OPS + i] = g_yim[xoff];
    }
    if (threadIdx.x < 64) {
        int o = threadIdx.x;
        float r = 0.f, m = 0.f;
#pragma unroll
        for (int d = 0; d < 16; d++) {
            float a = ner[v * 16 + d], b2 = nei[v * 16 + d];
            float pr = bre[d * 64 + o], pi = bim[d * 64 + o];
            r += a * pr - b2 * pi;
            m += a * pi + b2 * pr;
        }
        br[o] = r;
        bi[o] = m;
    }
    __syncthreads();

    int og = (threadIdx.x & 15) * 4;
    int bg = (threadIdx.x >> 4) * 4;
    float accR[4][4] = {}, accI[4][4] = {};
#pragma unroll 8
    for (int i = 0; i < 64; i++) {
        float xv[4], yrv[4], yiv[4];
#pragma unroll
        for (int b = 0; b < 4; b++) {
            int base = (bg + b) * OPS + i;
            xv[b] = xs[base];
            yrv[b] = yr[base];
            yiv[b] = yi[base];
        }
        float4 a4 = *(const float4*)&Ar[i * 64 + og];
        float4 b4 = *(const float4*)&Ai[i * 64 + og];
        float4 c4 = *(const float4*)&Cr[i * 64 + og];
        float4 d4 = *(const float4*)&Ci[i * 64 + og];
        float ar_[4] = {a4.x, a4.y, a4.z, a4.w};
        float ai_[4] = {b4.x, b4.y, b4.z, b4.w};
        float cr_[4] = {c4.x, c4.y, c4.z, c4.w};
        float ci_[4] = {d4.x, d4.y, d4.z, d4.w};
#pragma unroll
        for (int b = 0; b < 4; b++) {
#pragma unroll
            for (int oo = 0; oo < 4; oo++) {
                accR[b][oo] += xv[b] * ar_[oo] + yrv[b] * cr_[oo] - yiv[b] * ci_[oo];
                accI[b][oo] += xv[b] * ai_[oo] + yrv[b] * ci_[oo] + yiv[b] * cr_[oo];
            }
        }
    }
#pragma unroll
    for (int b = 0; b < 4; b++) {
        int bidx = bg + b;
        size_t ob = ((size_t)bidx * VV + v) * 128 + 2 * og;
        float buf[8];
#pragma unroll
        for (int oo = 0; oo < 4; oo++) {
            buf[2 * oo]     = accR[b][oo] + br[og + oo];
            buf[2 * oo + 1] = accI[b][oo] + bi[og + oo];
        }
        *(float4*)&out[ob]     = *(float4*)&buf[0];
        *(float4*)&out[ob + 4] = *(float4*)&buf[4];
    }
}

extern "C" void kernel_launch(void* const* d_in, const int* in_sizes, int n_in,
                              void* d_out, int out_size) {
    const float* x   = (const float*)d_in[0];
    const float* ner = (const float*)d_in[1];
    const float* nei = (const float*)d_in[2];
    const float* wr  = (const float*)d_in[3];
    const float* wi  = (const float*)d_in[4];
    const float* bre = (const float*)d_in[5];
    const float* bim = (const float*)d_in[6];
    float* out = (float*)d_out;

    int smem_out = (16384 + 3 * 64 * OPS + 128) * 4;
    cudaFuncSetAttribute(out_kernel, cudaFuncAttributeMaxDynamicSharedMemorySize, smem_out);

    k1_gram_z<<<32 + BB * 4, 256>>>(x, ner, nei);            // L1
    y_kernel<<<BB * 32, 256>>>(ner, nei);                    // L2
    wcomb_kernel<<<dim3(16, 20), 256>>>(ner, nei, wr, wi);   // L3
    out_kernel<<<VV, 256, smem_out>>>(x, ner, nei, bre, bim, out);  // L4 (ncu target)
}

// round 8
// speedup vs baseline: 1.2295x; 1.2295x over previous
#include <cuda_runtime.h>

#define BB 64
#define VV 2000
#define DD 16
#define CI 64
#define CO 64

// ---------------- scratch (device globals, no allocation) ----------------
__device__ float g_partG[32 * 512];
__device__ float g_Zre[BB * DD * CI];
__device__ float g_Zim[BB * DD * CI];
__device__ float g_yre[(size_t)BB * VV * CI];
__device__ float g_yim[(size_t)BB * VV * CI];
__device__ float4 g_AC4[(size_t)VV * CI * CO];   // (Ar, Ai, Cr, Ci)

// ================ K1: gram_partial (blocks 0-31) + z (blocks 32-287) ================
__global__ void __launch_bounds__(256) k1_gram_z(const float* __restrict__ x,
                                                 const float* __restrict__ ner,
                                                 const float* __restrict__ nei) {
    __shared__ float sm[4608];
    if (blockIdx.x < 32) {
        float* sr = sm;
        float* si = sm + 1008;
        int blk = blockIdx.x;
        int v0 = blk * 63;
        int cnt = min(63, VV - v0);
        for (int t = threadIdx.x; t < cnt * 16; t += 256) {
            sr[t] = ner[v0 * 16 + t];
            si[t] = nei[v0 * 16 + t];
        }
        __syncthreads();
        int d = threadIdx.x >> 4, e = threadIdx.x & 15;
        float ar = 0.f, ai = 0.f;
        for (int vv = 0; vv < cnt; vv++) {
            float a = sr[vv * 16 + d], b = si[vv * 16 + d];
            float c = sr[vv * 16 + e], dd = si[vv * 16 + e];
            ar += a * c + b * dd;
            ai += a * dd - b * c;
        }
        g_partG[blk * 512 + threadIdx.x * 2]     = ar;
        g_partG[blk * 512 + threadIdx.x * 2 + 1] = ai;
    } else {
        // z: Z[b,d,i] = sum_v conj(ne[v,d]) * x[b,v,i]
        float* xs = sm;
        float* nr = sm + 4096;
        float* ni = sm + 4352;
        int bx = blockIdx.x - 32;
        int b = bx >> 2;
        int d0 = (bx & 3) * 4;
        int i = threadIdx.x & 63;
        int dl = threadIdx.x >> 6;
        float ar = 0.f, ai = 0.f;
        for (int v0 = 0; v0 < VV; v0 += 64) {
            int cnt = min(64, VV - v0);
            __syncthreads();
            for (int t = threadIdx.x; t < cnt * 64; t += 256)
                xs[t] = x[(size_t)b * VV * 64 + (size_t)v0 * 64 + t];
            for (int t = threadIdx.x; t < cnt * 4; t += 256) {
                int vv = t >> 2, dd = t & 3;
                nr[t] = ner[(v0 + vv) * 16 + d0 + dd];
                ni[t] = nei[(v0 + vv) * 16 + d0 + dd];
            }
            __syncthreads();
            for (int vv = 0; vv < cnt; vv++) {
                float xv = xs[vv * 64 + i];
                ar += nr[vv * 4 + dl] * xv;
                ai -= ni[vv * 4 + dl] * xv;
            }
        }
        g_Zre[(b * 16 + d0 + dl) * 64 + i] = ar;
        g_Zim[(b * 16 + d0 + dl) * 64 + i] = ai;
    }
}

// ================ K2: y ================
__global__ void __launch_bounds__(256) y_kernel(const float* __restrict__ ner,
                                                const float* __restrict__ nei) {
    __shared__ float sm[4096];
    float* Zr = sm;
    float* Zi = sm + 1024;
    float* nr = sm + 2048;
    float* ni = sm + 3072;
    int b = blockIdx.x >> 5;
    int v0 = (blockIdx.x & 31) * 64;
    int vcnt = min(64, VV - v0);
    for (int t = threadIdx.x; t < 1024; t += 256) {
        Zr[t] = g_Zre[b * 1024 + t];
        Zi[t] = g_Zim[b * 1024 + t];
    }
    for (int t = threadIdx.x; t < vcnt * 16; t += 256) {
        nr[t] = ner[v0 * 16 + t];
        ni[t] = nei[v0 * 16 + t];
    }
    __syncthreads();
    int i = threadIdx.x & 63;
    int vb = threadIdx.x >> 6;
    float zr[16], zi[16];
#pragma unroll
    for (int d = 0; d < 16; d++) { zr[d] = Zr[d * 64 + i]; zi[d] = Zi[d * 64 + i]; }
    for (int vl = vb; vl < vcnt; vl += 4) {
        float yr = 0.f, yi = 0.f;
#pragma unroll
        for (int d = 0; d < 16; d++) {
            float a = nr[vl * 16 + d], c = ni[vl * 16 + d];
            yr += a * zr[d] - c * zi[d];
            yi += a * zi[d] + c * zr[d];
        }
        size_t o = (size_t)b * VV * 64 + (size_t)(v0 + vl) * 64 + i;
        g_yre[o] = yr;
        g_yim[o] = yi;
    }
}

// ================ K3: wcomb (inline gram reduce + float4 stores) ================
__global__ void __launch_bounds__(256) wcomb_kernel(const float* __restrict__ ner,
                                                    const float* __restrict__ nei,
                                                    const float* __restrict__ wr,
                                                    const float* __restrict__ wi) {
    __shared__ float red[256];
    __shared__ float s_inv;
    __shared__ float nr[100 * 16], ni[100 * 16];
    int t = threadIdx.x;
    {
        float gr = 0.f, gi = 0.f;
        for (int blk = 0; blk < 32; blk++) {
            gr += g_partG[blk * 512 + t * 2];
            gi += g_partG[blk * 512 + t * 2 + 1];
        }
        red[t] = gr * gr + gi * gi;
        __syncthreads();
        for (int s = 128; s > 0; s >>= 1) {
            if (t < s) red[t] += red[t + s];
            __syncthreads();
        }
        if (t == 0) s_inv = rsqrtf(red[0]);
    }

    int io = blockIdx.x * 256 + t;
    int vstart = blockIdx.y * 100;
    for (int n = t; n < 100 * 16; n += 256) {
        nr[n] = ner[vstart * 16 + n];
        ni[n] = nei[vstart * 16 + n];
    }
    __syncthreads();
    float s = s_inv;
    float P0r[16], P0i[16], P1r[16], P1i[16];
#pragma unroll
    for (int d = 0; d < 16; d++) {
        float r0 = wr[(d * 3 + 0) * 4096 + io];
        float r1 = wr[(d * 3 + 1) * 4096 + io];
        float r2 = wr[(d * 3 + 2) * 4096 + io];
        float i0 = wi[(d * 3 + 0) * 4096 + io];
        float i1 = wi[(d * 3 + 1) * 4096 + io];
        float i2 = wi[(d * 3 + 2) * 4096 + io];
        P0r[d] = r0 - r2;
        P0i[d] = i0 - i2;
        P1r[d] = (r1 + 2.f * r2) * s;
        P1i[d] = (i1 + 2.f * i2) * s;
    }
    for (int vl = 0; vl < 100; vl++) {
        float Ar = 0.f, Ai = 0.f, Cr = 0.f, Ci = 0.f;
#pragma unroll
        for (int d = 0; d < 16; d++) {
            float a = nr[vl * 16 + d], b = ni[vl * 16 + d];
            Ar += a * P0r[d] - b * P0i[d];
            Ai += a * P0i[d] + b * P0r[d];
            Cr += a * P1r[d] - b * P1i[d];
            Ci += a * P1i[d] + b * P1r[d];
        }
        g_AC4[(size_t)(vstart + vl) * 4096 + io] = make_float4(Ar, Ai, Cr, Ci);
    }
}

// ================ K4: final per-node GEMM (R6 geometry: 28800 floats smem) ================
__global__ void __launch_bounds__(256) out_kernel(const float* __restrict__ x,
                                                  const float* __restrict__ ner,
                                                  const float* __restrict__ nei,
                                                  const float* __restrict__ bre,
                                                  const float* __restrict__ bim,
                                                  float* __restrict__ out) {
    extern __shared__ float sm[];
    float* Ar = sm;            // 4096
    float* Ai = sm + 4096;
    float* Cr = sm + 8192;
    float* Ci = sm + 12288;
    float* xs = sm + 16384;    // 4096 : [b][i] stride 64
    float* yr = sm + 20480;
    float* yi = sm + 24576;
    float* br = sm + 28672;    // 64
    float* bi = sm + 28736;

    int v = blockIdx.x;
    size_t vo = (size_t)v * 4096;
    for (int t = threadIdx.x; t < 4096; t += 256) {
        float4 c = g_AC4[vo + t];
        Ar[t] = c.x; Ai[t] = c.y; Cr[t] = c.z; Ci[t] = c.w;
        int b = t >> 6, i = t & 63;
        size_t xoff = (size_t)b * (VV * 64) + (size_t)v * 64 + i;
        xs[t] = x[xoff];
        yr[t] = g_yre[xoff];
        yi[t] = g_yim[xoff];
    }
    if (threadIdx.x < 64) {
        int o = threadIdx.x;
        float r = 0.f, m = 0.f;
#pragma unroll
        for (int d = 0; d < 16; d++) {
            float a = ner[v * 16 + d], b2 = nei[v * 16 + d];
            float pr = bre[d * 64 + o], pi = bim[d * 64 + o];
            r += a * pr - b2 * pi;
            m += a * pi + b2 * pr;
        }
        br[o] = r;
        bi[o] = m;
    }
    __syncthreads();

    int og = (threadIdx.x & 15) * 4;
    int bg = (threadIdx.x >> 4) * 4;
    float accR[4][4] = {}, accI[4][4] = {};
#pragma unroll 4
    for (int i = 0; i < 64; i++) {
        float xv[4], yrv[4], yiv[4];
#pragma unroll
        for (int b = 0; b < 4; b++) {
            int base = (bg + b) * 64 + i;
            xv[b] = xs[base];
            yrv[b] = yr[base];
            yiv[b] = yi[base];
        }
        float4 a4 = *(const float4*)&Ar[i * 64 + og];
        float4 b4 = *(const float4*)&Ai[i * 64 + og];
        float4 c4 = *(const float4*)&Cr[i * 64 + og];
        float4 d4 = *(const float4*)&Ci[i * 64 + og];
        float ar_[4] = {a4.x, a4.y, a4.z, a4.w};
        float ai_[4] = {b4.x, b4.y, b4.z, b4.w};
        float cr_[4] = {c4.x, c4.y, c4.z, c4.w};
        float ci_[4] = {d4.x, d4.y, d4.z, d4.w};
#pragma unroll
        for (int b = 0; b < 4; b++) {
#pragma unroll
            for (int oo = 0; oo < 4; oo++) {
                accR[b][oo] += xv[b] * ar_[oo] + yrv[b] * cr_[oo] - yiv[b] * ci_[oo];
                accI[b][oo] += xv[b] * ai_[oo] + yrv[b] * ci_[oo] + yiv[b] * cr_[oo];
            }
        }
    }
#pragma unroll
    for (int b = 0; b < 4; b++) {
        int bidx = bg + b;
        size_t ob = ((size_t)bidx * VV + v) * 128 + 2 * og;
        float buf[8];
#pragma unroll
        for (int oo = 0; oo < 4; oo++) {
            buf[2 * oo]     = accR[b][oo] + br[og + oo];
            buf[2 * oo + 1] = accI[b][oo] + bi[og + oo];
        }
        *(float4*)&out[ob]     = *(float4*)&buf[0];
        *(float4*)&out[ob + 4] = *(float4*)&buf[4];
    }
}

extern "C" void kernel_launch(void* const* d_in, const int* in_sizes, int n_in,
                              void* d_out, int out_size) {
    const float* x   = (const float*)d_in[0];
    const float* ner = (const float*)d_in[1];
    const float* nei = (const float*)d_in[2];
    const float* wr  = (const float*)d_in[3];
    const float* wi  = (const float*)d_in[4];
    const float* bre = (const float*)d_in[5];
    const float* bim = (const float*)d_in[6];
    float* out = (float*)d_out;

    cudaFuncSetAttribute(out_kernel, cudaFuncAttributeMaxDynamicSharedMemorySize, 28800 * 4);

    k1_gram_z<<<32 + BB * 4, 256>>>(x, ner, nei);            // L1
    y_kernel<<<BB * 32, 256>>>(ner, nei);                    // L2
    wcomb_kernel<<<dim3(16, 20), 256>>>(ner, nei, wr, wi);   // L3
    out_kernel<<<VV, 256, 28800 * 4>>>(x, ner, nei, bre, bim, out);  // L4 (ncu target)
}

// round 9
// speedup vs baseline: 1.5677x; 1.2750x over previous
#include <cuda_runtime.h>

#define BB 64
#define VV 2000
#define DD 16
#define CI 64
#define CO 64
#define VHALF 1000
#define VTILE 128

// ---------------- scratch (device globals, no allocation) ----------------
__device__ float g_partG[32 * 512];
__device__ float g_inv_norm;
__device__ float g_Zre[2 * BB * DD * CI];   // [half][b][d][i]
__device__ float g_Zim[2 * BB * DD * CI];
__device__ float g_yre[(size_t)BB * VV * CI];
__device__ float g_yim[(size_t)BB * VV * CI];
__device__ float4 g_AC4[(size_t)VV * CI * CO];   // (Ar, Ai, Cr, Ci)

// ================ K1: gram_partial (blocks 0-31) + z (blocks 32-159) ================
__global__ void __launch_bounds__(256) k1_gram_z(const float* __restrict__ x,
                                                 const float* __restrict__ ner,
                                                 const float* __restrict__ nei) {
    __shared__ float xs[VTILE * 64];          // 32 KB
    __shared__ float2 ns[VTILE * 16];         // 16 KB  (re,im per (v,d))
    if (blockIdx.x < 32) {
        float* sr = xs;                       // 1008
        float* si = xs + 1024;
        int blk = blockIdx.x;
        int v0 = blk * 63;
        int cnt = min(63, VV - v0);
        for (int t = threadIdx.x; t < cnt * 16; t += 256) {
            sr[t] = ner[v0 * 16 + t];
            si[t] = nei[v0 * 16 + t];
        }
        __syncthreads();
        int d = threadIdx.x >> 4, e = threadIdx.x & 15;
        float ar = 0.f, ai = 0.f;
        for (int vv = 0; vv < cnt; vv++) {
            float a = sr[vv * 16 + d], b = si[vv * 16 + d];
            float c = sr[vv * 16 + e], dd = si[vv * 16 + e];
            ar += a * c + b * dd;
            ai += a * dd - b * c;
        }
        g_partG[blk * 512 + threadIdx.x * 2]     = ar;
        g_partG[blk * 512 + threadIdx.x * 2 + 1] = ai;
    } else {
        // z: Z[half][b][d][i] = sum_{v in half} conj(ne[v,d]) * x[b,v,i]
        int bx = blockIdx.x - 32;             // 0..127
        int b = bx >> 1;
        int half = bx & 1;
        int vbase = half * VHALF;
        int ig = threadIdx.x & 63;
        int dg = threadIdx.x >> 6;            // 0..3 -> d = dg*4..dg*4+3
        float ar[4] = {}, ai[4] = {};
        for (int v0 = 0; v0 < VHALF; v0 += VTILE) {
            int cnt = min(VTILE, VHALF - v0);
            __syncthreads();
            // fill x tile: rows of 64 floats, coalesced float4
            {
                const float4* src = (const float4*)(x + (size_t)b * VV * 64 + (size_t)(vbase + v0) * 64);
                float4* dst = (float4*)xs;
                for (int t = threadIdx.x; t < cnt * 16; t += 256) dst[t] = src[t];
            }
            // fill ne tile
            for (int t = threadIdx.x; t < cnt * 16; t += 256) {
                int vv = t >> 4, d = t & 15;
                ns[vv * 16 + d] = make_float2(ner[(vbase + v0 + vv) * 16 + d],
                                              nei[(vbase + v0 + vv) * 16 + d]);
            }
            __syncthreads();
#pragma unroll 4
            for (int vv = 0; vv < cnt; vv++) {
                float xv = xs[vv * 64 + ig];
                float2 n0 = ns[vv * 16 + dg * 4 + 0];
                float2 n1 = ns[vv * 16 + dg * 4 + 1];
                float2 n2 = ns[vv * 16 + dg * 4 + 2];
                float2 n3 = ns[vv * 16 + dg * 4 + 3];
                ar[0] += n0.x * xv; ai[0] -= n0.y * xv;
                ar[1] += n1.x * xv; ai[1] -= n1.y * xv;
                ar[2] += n2.x * xv; ai[2] -= n2.y * xv;
                ar[3] += n3.x * xv; ai[3] -= n3.y * xv;
            }
        }
#pragma unroll
        for (int k = 0; k < 4; k++) {
            int idx = ((half * BB + b) * 16 + dg * 4 + k) * 64 + ig;
            g_Zre[idx] = ar[k];
            g_Zim[idx] = ai[k];
        }
    }
}

// ================ K2: gram_reduce (block 0) + y (blocks 1-2048) ================
__global__ void __launch_bounds__(256) k2_reduce_y(const float* __restrict__ ner,
                                                   const float* __restrict__ nei) {
    __shared__ float sm[4096];
    if (blockIdx.x == 0) {
        float* red = sm;
        int t = threadIdx.x;
        float gr = 0.f, gi = 0.f;
        for (int blk = 0; blk < 32; blk++) {
            gr += g_partG[blk * 512 + t * 2];
            gi += g_partG[blk * 512 + t * 2 + 1];
        }
        red[t] = gr * gr + gi * gi;
        __syncthreads();
        for (int s = 128; s > 0; s >>= 1) {
            if (t < s) red[t] += red[t + s];
            __syncthreads();
        }
        if (t == 0) g_inv_norm = rsqrtf(red[0]);
    } else {
        float* Zr = sm;
        float* Zi = sm + 1024;
        float* nr = sm + 2048;
        float* ni = sm + 3072;
        int bx = blockIdx.x - 1;
        int b = bx >> 5;
        int v0 = (bx & 31) * 64;
        int vcnt = min(64, VV - v0);
        for (int t = threadIdx.x; t < 1024; t += 256) {
            Zr[t] = g_Zre[b * 1024 + t] + g_Zre[65536 + b * 1024 + t];
            Zi[t] = g_Zim[b * 1024 + t] + g_Zim[65536 + b * 1024 + t];
        }
        for (int t = threadIdx.x; t < vcnt * 16; t += 256) {
            nr[t] = ner[v0 * 16 + t];
            ni[t] = nei[v0 * 16 + t];
        }
        __syncthreads();
        int i = threadIdx.x & 63;
        int vb = threadIdx.x >> 6;
        float zr[16], zi[16];
#pragma unroll
        for (int d = 0; d < 16; d++) { zr[d] = Zr[d * 64 + i]; zi[d] = Zi[d * 64 + i]; }
        for (int vl = vb; vl < vcnt; vl += 4) {
            float yr = 0.f, yi = 0.f;
#pragma unroll
            for (int d = 0; d < 16; d++) {
                float a = nr[vl * 16 + d], c = ni[vl * 16 + d];
                yr += a * zr[d] - c * zi[d];
                yi += a * zi[d] + c * zr[d];
            }
            size_t o = (size_t)b * VV * 64 + (size_t)(v0 + vl) * 64 + i;
            g_yre[o] = yr;
            g_yim[o] = yi;
        }
    }
}

// ================ K3: wcomb (reads g_inv_norm, float4 stores) ================
__global__ void __launch_bounds__(256) wcomb_kernel(const float* __restrict__ ner,
                                                    const float* __restrict__ nei,
                                                    const float* __restrict__ wr,
                                                    const float* __restrict__ wi) {
    int io = blockIdx.x * 256 + threadIdx.x;
    int vstart = blockIdx.y * 100;
    float s = g_inv_norm;
    float P0r[16], P0i[16], P1r[16], P1i[16];
#pragma unroll
    for (int d = 0; d < 16; d++) {
        float r0 = wr[(d * 3 + 0) * 4096 + io];
        float r1 = wr[(d * 3 + 1) * 4096 + io];
        float r2 = wr[(d * 3 + 2) * 4096 + io];
        float i0 = wi[(d * 3 + 0) * 4096 + io];
        float i1 = wi[(d * 3 + 1) * 4096 + io];
        float i2 = wi[(d * 3 + 2) * 4096 + io];
        P0r[d] = r0 - r2;
        P0i[d] = i0 - i2;
        P1r[d] = (r1 + 2.f * r2) * s;
        P1i[d] = (i1 + 2.f * i2) * s;
    }
    __shared__ float nr[100 * 16], ni[100 * 16];
    for (int t = threadIdx.x; t < 100 * 16; t += 256) {
        nr[t] = ner[vstart * 16 + t];
        ni[t] = nei[vstart * 16 + t];
    }
    __syncthreads();
    for (int vl = 0; vl < 100; vl++) {
        float Ar = 0.f, Ai = 0.f, Cr = 0.f, Ci = 0.f;
#pragma unroll
        for (int d = 0; d < 16; d++) {
            float a = nr[vl * 16 + d], b = ni[vl * 16 + d];
            Ar += a * P0r[d] - b * P0i[d];
            Ai += a * P0i[d] + b * P0r[d];
            Cr += a * P1r[d] - b * P1i[d];
            Ci += a * P1i[d] + b * P1r[d];
        }
        g_AC4[(size_t)(vstart + vl) * 4096 + io] = make_float4(Ar, Ai, Cr, Ci);
    }
}

// ================ K4: final per-node GEMM (R8 body, unchanged) ================
__global__ void __launch_bounds__(256) out_kernel(const float* __restrict__ x,
                                                  const float* __restrict__ ner,
                                                  const float* __restrict__ nei,
                                                  const float* __restrict__ bre,
                                                  const float* __restrict__ bim,
                                                  float* __restrict__ out) {
    extern __shared__ float sm[];
    float* Ar = sm;            // 4096
    float* Ai = sm + 4096;
    float* Cr = sm + 8192;
    float* Ci = sm + 12288;
    float* xs = sm + 16384;    // [b][i] stride 64
    float* yr = sm + 20480;
    float* yi = sm + 24576;
    float* br = sm + 28672;
    float* bi = sm + 28736;

    int v = blockIdx.x;
    size_t vo = (size_t)v * 4096;
    for (int t = threadIdx.x; t < 4096; t += 256) {
        float4 c = g_AC4[vo + t];
        Ar[t] = c.x; Ai[t] = c.y; Cr[t] = c.z; Ci[t] = c.w;
        int b = t >> 6, i = t & 63;
        size_t xoff = (size_t)b * (VV * 64) + (size_t)v * 64 + i;
        xs[t] = x[xoff];
        yr[t] = g_yre[xoff];
        yi[t] = g_yim[xoff];
    }
    if (threadIdx.x < 64) {
        int o = threadIdx.x;
        float r = 0.f, m = 0.f;
#pragma unroll
        for (int d = 0; d < 16; d++) {
            float a = ner[v * 16 + d], b2 = nei[v * 16 + d];
            float pr = bre[d * 64 + o], pi = bim[d * 64 + o];
            r += a * pr - b2 * pi;
            m += a * pi + b2 * pr;
        }
        br[o] = r;
        bi[o] = m;
    }
    __syncthreads();

    int og = (threadIdx.x & 15) * 4;
    int bg = (threadIdx.x >> 4) * 4;
    float accR[4][4] = {}, accI[4][4] = {};
#pragma unroll 4
    for (int i = 0; i < 64; i++) {
        float xv[4], yrv[4], yiv[4];
#pragma unroll
        for (int b = 0; b < 4; b++) {
            int base = (bg + b) * 64 + i;
            xv[b] = xs[base];
            yrv[b] = yr[base];
            yiv[b] = yi[base];
        }
        float4 a4 = *(const float4*)&Ar[i * 64 + og];
        float4 b4 = *(const float4*)&Ai[i * 64 + og];
        float4 c4 = *(const float4*)&Cr[i * 64 + og];
        float4 d4 = *(const float4*)&Ci[i * 64 + og];
        float ar_[4] = {a4.x, a4.y, a4.z, a4.w};
        float ai_[4] = {b4.x, b4.y, b4.z, b4.w};
        float cr_[4] = {c4.x, c4.y, c4.z, c4.w};
        float ci_[4] = {d4.x, d4.y, d4.z, d4.w};
#pragma unroll
        for (int b = 0; b < 4; b++) {
#pragma unroll
            for (int oo = 0; oo < 4; oo++) {
                accR[b][oo] += xv[b] * ar_[oo] + yrv[b] * cr_[oo] - yiv[b] * ci_[oo];
                accI[b][oo] += xv[b] * ai_[oo] + yrv[b] * ci_[oo] + yiv[b] * cr_[oo];
            }
        }
    }
#pragma unroll
    for (int b = 0; b < 4; b++) {
        int bidx = bg + b;
        size_t ob = ((size_t)bidx * VV + v) * 128 + 2 * og;
        float buf[8];
#pragma unroll
        for (int oo = 0; oo < 4; oo++) {
            buf[2 * oo]     = accR[b][oo] + br[og + oo];
            buf[2 * oo + 1] = accI[b][oo] + bi[og + oo];
        }
        *(float4*)&out[ob]     = *(float4*)&buf[0];
        *(float4*)&out[ob + 4] = *(float4*)&buf[4];
    }
}

extern "C" void kernel_launch(void* const* d_in, const int* in_sizes, int n_in,
                              void* d_out, int out_size) {
    const float* x   = (const float*)d_in[0];
    const float* ner = (const float*)d_in[1];
    const float* nei = (const float*)d_in[2];
    const float* wr  = (const float*)d_in[3];
    const float* wi  = (const float*)d_in[4];
    const float* bre = (const float*)d_in[5];
    const float* bim = (const float*)d_in[6];
    float* out = (float*)d_out;

    cudaFuncSetAttribute(out_kernel, cudaFuncAttributeMaxDynamicSharedMemorySize, 28800 * 4);

    k1_gram_z<<<32 + 2 * BB, 256>>>(x, ner, nei);            // L1
    k2_reduce_y<<<1 + BB * 32, 256>>>(ner, nei);             // L2
    wcomb_kernel<<<dim3(16, 20), 256>>>(ner, nei, wr, wi);   // L3
    out_kernel<<<VV, 256, 28800 * 4>>>(x, ner, nei, bre, bim, out);  // L4 (ncu target)
}

// round 10
// speedup vs baseline: 1.6653x; 1.0623x over previous
#include <cuda_runtime.h>

#define BB 64
#define VV 2000
#define DD 16
#define CI 64
#define CO 64
#define VHALF 1000
#define VTILE 128
#define WVB 36    // v per wcomb block

// ---------------- scratch (device globals, no allocation) ----------------
__device__ float g_partG[32 * 512];
__device__ float g_inv_norm;
__device__ float g_Zre[2 * BB * DD * CI];   // [half][b][d][i]
__device__ float g_Zim[2 * BB * DD * CI];
__device__ float2 g_y[(size_t)BB * VV * CI];     // (yr, yi) interleaved
__device__ float4 g_AC4[(size_t)VV * CI * CO];   // (Ar, Ai, Cr, Ci)

// ================ K1: gram_partial (blocks 0-31) + z (blocks 32-159) ================
__global__ void __launch_bounds__(256) k1_gram_z(const float* __restrict__ x,
                                                 const float* __restrict__ ner,
                                                 const float* __restrict__ nei) {
    __shared__ float xs[VTILE * 64];
    __shared__ float2 ns[VTILE * 16];
    if (blockIdx.x < 32) {
        float* sr = xs;
        float* si = xs + 1024;
        int blk = blockIdx.x;
        int v0 = blk * 63;
        int cnt = min(63, VV - v0);
        for (int t = threadIdx.x; t < cnt * 16; t += 256) {
            sr[t] = ner[v0 * 16 + t];
            si[t] = nei[v0 * 16 + t];
        }
        __syncthreads();
        int d = threadIdx.x >> 4, e = threadIdx.x & 15;
        float ar = 0.f, ai = 0.f;
        for (int vv = 0; vv < cnt; vv++) {
            float a = sr[vv * 16 + d], b = si[vv * 16 + d];
            float c = sr[vv * 16 + e], dd = si[vv * 16 + e];
            ar += a * c + b * dd;
            ai += a * dd - b * c;
        }
        g_partG[blk * 512 + threadIdx.x * 2]     = ar;
        g_partG[blk * 512 + threadIdx.x * 2 + 1] = ai;
    } else {
        int bx = blockIdx.x - 32;
        int b = bx >> 1;
        int half = bx & 1;
        int vbase = half * VHALF;
        int ig = threadIdx.x & 63;
        int dg = threadIdx.x >> 6;
        float ar[4] = {}, ai[4] = {};
        for (int v0 = 0; v0 < VHALF; v0 += VTILE) {
            int cnt = min(VTILE, VHALF - v0);
            __syncthreads();
            {
                const float4* src = (const float4*)(x + (size_t)b * VV * 64 + (size_t)(vbase + v0) * 64);
                float4* dst = (float4*)xs;
                for (int t = threadIdx.x; t < cnt * 16; t += 256) dst[t] = src[t];
            }
            for (int t = threadIdx.x; t < cnt * 16; t += 256) {
                int vv = t >> 4, d = t & 15;
                ns[vv * 16 + d] = make_float2(ner[(vbase + v0 + vv) * 16 + d],
                                              nei[(vbase + v0 + vv) * 16 + d]);
            }
            __syncthreads();
#pragma unroll 4
            for (int vv = 0; vv < cnt; vv++) {
                float xv = xs[vv * 64 + ig];
                float2 n0 = ns[vv * 16 + dg * 4 + 0];
                float2 n1 = ns[vv * 16 + dg * 4 + 1];
                float2 n2 = ns[vv * 16 + dg * 4 + 2];
                float2 n3 = ns[vv * 16 + dg * 4 + 3];
                ar[0] += n0.x * xv; ai[0] -= n0.y * xv;
                ar[1] += n1.x * xv; ai[1] -= n1.y * xv;
                ar[2] += n2.x * xv; ai[2] -= n2.y * xv;
                ar[3] += n3.x * xv; ai[3] -= n3.y * xv;
            }
        }
#pragma unroll
        for (int k = 0; k < 4; k++) {
            int idx = ((half * BB + b) * 16 + dg * 4 + k) * 64 + ig;
            g_Zre[idx] = ar[k];
            g_Zim[idx] = ai[k];
        }
    }
}

// ================ K2: gram_reduce (block 0) + y (blocks 1-2048) ================
__global__ void __launch_bounds__(256) k2_reduce_y(const float* __restrict__ ner,
                                                   const float* __restrict__ nei) {
    __shared__ float sm[4096];
    if (blockIdx.x == 0) {
        float* red = sm;
        int t = threadIdx.x;
        float gr = 0.f, gi = 0.f;
        for (int blk = 0; blk < 32; blk++) {
            gr += g_partG[blk * 512 + t * 2];
            gi += g_partG[blk * 512 + t * 2 + 1];
        }
        red[t] = gr * gr + gi * gi;
        __syncthreads();
        for (int s = 128; s > 0; s >>= 1) {
            if (t < s) red[t] += red[t + s];
            __syncthreads();
        }
        if (t == 0) g_inv_norm = rsqrtf(red[0]);
    } else {
        float* Zr = sm;
        float* Zi = sm + 1024;
        float* nr = sm + 2048;
        float* ni = sm + 3072;
        int bx = blockIdx.x - 1;
        int b = bx >> 5;
        int v0 = (bx & 31) * 64;
        int vcnt = min(64, VV - v0);
        for (int t = threadIdx.x; t < 1024; t += 256) {
            Zr[t] = g_Zre[b * 1024 + t] + g_Zre[65536 + b * 1024 + t];
            Zi[t] = g_Zim[b * 1024 + t] + g_Zim[65536 + b * 1024 + t];
        }
        for (int t = threadIdx.x; t < vcnt * 16; t += 256) {
            nr[t] = ner[v0 * 16 + t];
            ni[t] = nei[v0 * 16 + t];
        }
        __syncthreads();
        int i = threadIdx.x & 63;
        int vb = threadIdx.x >> 6;
        float zr[16], zi[16];
#pragma unroll
        for (int d = 0; d < 16; d++) { zr[d] = Zr[d * 64 + i]; zi[d] = Zi[d * 64 + i]; }
        for (int vl = vb; vl < vcnt; vl += 4) {
            float yr = 0.f, yi = 0.f;
#pragma unroll
            for (int d = 0; d < 16; d++) {
                float a = nr[vl * 16 + d], c = ni[vl * 16 + d];
                yr += a * zr[d] - c * zi[d];
                yi += a * zi[d] + c * zr[d];
            }
            g_y[(size_t)b * VV * 64 + (size_t)(v0 + vl) * 64 + i] = make_float2(yr, yi);
        }
    }
}

// ================ K3: wcomb v2 — 2 io per thread, float2 pools ================
__global__ void __launch_bounds__(256) wcomb_kernel(const float* __restrict__ ner,
                                                    const float* __restrict__ nei,
                                                    const float* __restrict__ wr,
                                                    const float* __restrict__ wi) {
    int io2 = blockIdx.x * 256 + threadIdx.x;   // pair index 0..2047
    int io = io2 * 2;
    int vstart = blockIdx.y * WVB;
    int vcnt = min(WVB, VV - vstart);
    float s = g_inv_norm;
    float2 P0r[16], P0i[16], P1r[16], P1i[16];
#pragma unroll
    for (int d = 0; d < 16; d++) {
        float2 r0 = *(const float2*)&wr[(d * 3 + 0) * 4096 + io];
        float2 r1 = *(const float2*)&wr[(d * 3 + 1) * 4096 + io];
        float2 r2 = *(const float2*)&wr[(d * 3 + 2) * 4096 + io];
        float2 i0 = *(const float2*)&wi[(d * 3 + 0) * 4096 + io];
        float2 i1 = *(const float2*)&wi[(d * 3 + 1) * 4096 + io];
        float2 i2 = *(const float2*)&wi[(d * 3 + 2) * 4096 + io];
        P0r[d] = make_float2(r0.x - r2.x, r0.y - r2.y);
        P0i[d] = make_float2(i0.x - i2.x, i0.y - i2.y);
        P1r[d] = make_float2((r1.x + 2.f * r2.x) * s, (r1.y + 2.f * r2.y) * s);
        P1i[d] = make_float2((i1.x + 2.f * i2.x) * s, (i1.y + 2.f * i2.y) * s);
    }
    __shared__ float2 nsm[WVB * 16];
    for (int t = threadIdx.x; t < vcnt * 16; t += 256) {
        nsm[t] = make_float2(ner[vstart * 16 + t], nei[vstart * 16 + t]);
    }
    __syncthreads();
    for (int vl = 0; vl < vcnt; vl++) {
        float Ar0 = 0.f, Ai0 = 0.f, Cr0 = 0.f, Ci0 = 0.f;
        float Ar1 = 0.f, Ai1 = 0.f, Cr1 = 0.f, Ci1 = 0.f;
#pragma unroll
        for (int d = 0; d < 16; d++) {
            float2 n = nsm[vl * 16 + d];
            float a = n.x, b = n.y;
            Ar0 += a * P0r[d].x - b * P0i[d].x;
            Ai0 += a * P0i[d].x + b * P0r[d].x;
            Cr0 += a * P1r[d].x - b * P1i[d].x;
            Ci0 += a * P1i[d].x + b * P1r[d].x;
            Ar1 += a * P0r[d].y - b * P0i[d].y;
            Ai1 += a * P0i[d].y + b * P0r[d].y;
            Cr1 += a * P1r[d].y - b * P1i[d].y;
            Ci1 += a * P1i[d].y + b * P1r[d].y;
        }
        size_t off = (size_t)(vstart + vl) * 4096 + io;
        g_AC4[off]     = make_float4(Ar0, Ai0, Cr0, Ci0);
        g_AC4[off + 1] = make_float4(Ar1, Ai1, Cr1, Ci1);
    }
}

// ================ K4: final per-node GEMM (proven body; ncu target) ================
__global__ void __launch_bounds__(256) out_kernel(const float* __restrict__ x,
                                                  const float* __restrict__ ner,
                                                  const float* __restrict__ nei,
                                                  const float* __restrict__ bre,
                                                  const float* __restrict__ bim,
                                                  float* __restrict__ out) {
    extern __shared__ float sm[];
    float* Ar = sm;            // 4096
    float* Ai = sm + 4096;
    float* Cr = sm + 8192;
    float* Ci = sm + 12288;
    float* xs = sm + 16384;    // [b][i] stride 64
    float* yr = sm + 20480;
    float* yi = sm + 24576;
    float* br = sm + 28672;
    float* bi = sm + 28736;

    int v = blockIdx.x;
    size_t vo = (size_t)v * 4096;
    for (int t = threadIdx.x; t < 4096; t += 256) {
        float4 c = g_AC4[vo + t];
        Ar[t] = c.x; Ai[t] = c.y; Cr[t] = c.z; Ci[t] = c.w;
        int b = t >> 6, i = t & 63;
        size_t xoff = (size_t)b * (VV * 64) + (size_t)v * 64 + i;
        xs[t] = x[xoff];
        float2 yv = g_y[xoff];
        yr[t] = yv.x;
        yi[t] = yv.y;
    }
    if (threadIdx.x < 64) {
        int o = threadIdx.x;
        float r = 0.f, m = 0.f;
#pragma unroll
        for (int d = 0; d < 16; d++) {
            float a = ner[v * 16 + d], b2 = nei[v * 16 + d];
            float pr = bre[d * 64 + o], pi = bim[d * 64 + o];
            r += a * pr - b2 * pi;
            m += a * pi + b2 * pr;
        }
        br[o] = r;
        bi[o] = m;
    }
    __syncthreads();

    int og = (threadIdx.x & 15) * 4;
    int bg = (threadIdx.x >> 4) * 4;
    float accR[4][4] = {}, accI[4][4] = {};
#pragma unroll 4
    for (int i = 0; i < 64; i++) {
        float xv[4], yrv[4], yiv[4];
#pragma unroll
        for (int b = 0; b < 4; b++) {
            int base = (bg + b) * 64 + i;
            xv[b] = xs[base];
            yrv[b] = yr[base];
            yiv[b] = yi[base];
        }
        float4 a4 = *(const float4*)&Ar[i * 64 + og];
        float4 b4 = *(const float4*)&Ai[i * 64 + og];
        float4 c4 = *(const float4*)&Cr[i * 64 + og];
        float4 d4 = *(const float4*)&Ci[i * 64 + og];
        float ar_[4] = {a4.x, a4.y, a4.z, a4.w};
        float ai_[4] = {b4.x, b4.y, b4.z, b4.w};
        float cr_[4] = {c4.x, c4.y, c4.z, c4.w};
        float ci_[4] = {d4.x, d4.y, d4.z, d4.w};
#pragma unroll
        for (int b = 0; b < 4; b++) {
#pragma unroll
            for (int oo = 0; oo < 4; oo++) {
                accR[b][oo] += xv[b] * ar_[oo] + yrv[b] * cr_[oo] - yiv[b] * ci_[oo];
                accI[b][oo] += xv[b] * ai_[oo] + yrv[b] * ci_[oo] + yiv[b] * cr_[oo];
            }
        }
    }
#pragma unroll
    for (int b = 0; b < 4; b++) {
        int bidx = bg + b;
        size_t ob = ((size_t)bidx * VV + v) * 128 + 2 * og;
        float buf[8];
#pragma unroll
        for (int oo = 0; oo < 4; oo++) {
            buf[2 * oo]     = accR[b][oo] + br[og + oo];
            buf[2 * oo + 1] = accI[b][oo] + bi[og + oo];
        }
        *(float4*)&out[ob]     = *(float4*)&buf[0];
        *(float4*)&out[ob + 4] = *(float4*)&buf[4];
    }
}

extern "C" void kernel_launch(void* const* d_in, const int* in_sizes, int n_in,
                              void* d_out, int out_size) {
    const float* x   = (const float*)d_in[0];
    const float* ner = (const float*)d_in[1];
    const float* nei = (const float*)d_in[2];
    const float* wr  = (const float*)d_in[3];
    const float* wi  = (const float*)d_in[4];
    const float* bre = (const float*)d_in[5];
    const float* bim = (const float*)d_in[6];
    float* out = (float*)d_out;

    cudaFuncSetAttribute(out_kernel, cudaFuncAttributeMaxDynamicSharedMemorySize, 28800 * 4);

    k1_gram_z<<<32 + 2 * BB, 256>>>(x, ner, nei);             // L1
    k2_reduce_y<<<1 + BB * 32, 256>>>(ner, nei);              // L2
    wcomb_kernel<<<dim3(8, 56), 256>>>(ner, nei, wr, wi);     // L3
    out_kernel<<<VV, 256, 28800 * 4>>>(x, ner, nei, bre, bim, out);  // L4 (ncu target)
}

// round 12
// speedup vs baseline: 2.0086x; 1.2062x over previous
#include <cuda_runtime.h>
#include <cuda_bf16.h>
#include <cstdint>

#define BB 64
#define VV 2000
#define DD 16
#define CI 64
#define CO 64
#define VHALF 1000
#define VTILE 128
#define WVB 36

// ---------------- scratch ----------------
__device__ float g_partG[32 * 512];
__device__ float g_inv_norm;
__device__ float g_Zre[2 * BB * DD * CI];
__device__ float g_Zim[2 * BB * DD * CI];
__device__ float2 g_y[(size_t)BB * VV * CI];
__device__ float4 g_AC4[(size_t)VV * CI * CO];   // (Ar, Ai, Cr, Ci)

// ================ K1: gram_partial + z (unchanged, proven) ================
__global__ void __launch_bounds__(256) k1_gram_z(const float* __restrict__ x,
                                                 const float* __restrict__ ner,
                                                 const float* __restrict__ nei) {
    __shared__ float xs[VTILE * 64];
    __shared__ float2 ns[VTILE * 16];
    if (blockIdx.x < 32) {
        float* sr = xs;
        float* si = xs + 1024;
        int blk = blockIdx.x;
        int v0 = blk * 63;
        int cnt = min(63, VV - v0);
        for (int t = threadIdx.x; t < cnt * 16; t += 256) {
            sr[t] = ner[v0 * 16 + t];
            si[t] = nei[v0 * 16 + t];
        }
        __syncthreads();
        int d = threadIdx.x >> 4, e = threadIdx.x & 15;
        float ar = 0.f, ai = 0.f;
        for (int vv = 0; vv < cnt; vv++) {
            float a = sr[vv * 16 + d], b = si[vv * 16 + d];
            float c = sr[vv * 16 + e], dd = si[vv * 16 + e];
            ar += a * c + b * dd;
            ai += a * dd - b * c;
        }
        g_partG[blk * 512 + threadIdx.x * 2]     = ar;
        g_partG[blk * 512 + threadIdx.x * 2 + 1] = ai;
    } else {
        int bx = blockIdx.x - 32;
        int b = bx >> 1;
        int half = bx & 1;
        int vbase = half * VHALF;
        int ig = threadIdx.x & 63;
        int dg = threadIdx.x >> 6;
        float ar[4] = {}, ai[4] = {};
        for (int v0 = 0; v0 < VHALF; v0 += VTILE) {
            int cnt = min(VTILE, VHALF - v0);
            __syncthreads();
            {
                const float4* src = (const float4*)(x + (size_t)b * VV * 64 + (size_t)(vbase + v0) * 64);
                float4* dst = (float4*)xs;
                for (int t = threadIdx.x; t < cnt * 16; t += 256) dst[t] = src[t];
            }
            for (int t = threadIdx.x; t < cnt * 16; t += 256) {
                int vv = t >> 4, d = t & 15;
                ns[vv * 16 + d] = make_float2(ner[(vbase + v0 + vv) * 16 + d],
                                              nei[(vbase + v0 + vv) * 16 + d]);
            }
            __syncthreads();
#pragma unroll 4
            for (int vv = 0; vv < cnt; vv++) {
                float xv = xs[vv * 64 + ig];
                float2 n0 = ns[vv * 16 + dg * 4 + 0];
                float2 n1 = ns[vv * 16 + dg * 4 + 1];
                float2 n2 = ns[vv * 16 + dg * 4 + 2];
                float2 n3 = ns[vv * 16 + dg * 4 + 3];
                ar[0] += n0.x * xv; ai[0] -= n0.y * xv;
                ar[1] += n1.x * xv; ai[1] -= n1.y * xv;
                ar[2] += n2.x * xv; ai[2] -= n2.y * xv;
                ar[3] += n3.x * xv; ai[3] -= n3.y * xv;
            }
        }
#pragma unroll
        for (int k = 0; k < 4; k++) {
            int idx = ((half * BB + b) * 16 + dg * 4 + k) * 64 + ig;
            g_Zre[idx] = ar[k];
            g_Zim[idx] = ai[k];
        }
    }
}

// ================ K2: gram_reduce + y (unchanged) ================
__global__ void __launch_bounds__(256) k2_reduce_y(const float* __restrict__ ner,
                                                   const float* __restrict__ nei) {
    __shared__ float sm[4096];
    if (blockIdx.x == 0) {
        float* red = sm;
        int t = threadIdx.x;
        float gr = 0.f, gi = 0.f;
        for (int blk = 0; blk < 32; blk++) {
            gr += g_partG[blk * 512 + t * 2];
            gi += g_partG[blk * 512 + t * 2 + 1];
        }
        red[t] = gr * gr + gi * gi;
        __syncthreads();
        for (int s = 128; s > 0; s >>= 1) {
            if (t < s) red[t] += red[t + s];
            __syncthreads();
        }
        if (t == 0) g_inv_norm = rsqrtf(red[0]);
    } else {
        float* Zr = sm;
        float* Zi = sm + 1024;
        float* nr = sm + 2048;
        float* ni = sm + 3072;
        int bx = blockIdx.x - 1;
        int b = bx >> 5;
        int v0 = (bx & 31) * 64;
        int vcnt = min(64, VV - v0);
        for (int t = threadIdx.x; t < 1024; t += 256) {
            Zr[t] = g_Zre[b * 1024 + t] + g_Zre[65536 + b * 1024 + t];
            Zi[t] = g_Zim[b * 1024 + t] + g_Zim[65536 + b * 1024 + t];
        }
        for (int t = threadIdx.x; t < vcnt * 16; t += 256) {
            nr[t] = ner[v0 * 16 + t];
            ni[t] = nei[v0 * 16 + t];
        }
        __syncthreads();
        int i = threadIdx.x & 63;
        int vb = threadIdx.x >> 6;
        float zr[16], zi[16];
#pragma unroll
        for (int d = 0; d < 16; d++) { zr[d] = Zr[d * 64 + i]; zi[d] = Zi[d * 64 + i]; }
        for (int vl = vb; vl < vcnt; vl += 4) {
            float yr = 0.f, yi = 0.f;
#pragma unroll
            for (int d = 0; d < 16; d++) {
                float a = nr[vl * 16 + d], c = ni[vl * 16 + d];
                yr += a * zr[d] - c * zi[d];
                yi += a * zi[d] + c * zr[d];
            }
            g_y[(size_t)b * VV * 64 + (size_t)(v0 + vl) * 64 + i] = make_float2(yr, yi);
        }
    }
}

// ================ K3: wcomb (unchanged) ================
__global__ void __launch_bounds__(256) wcomb_kernel(const float* __restrict__ ner,
                                                    const float* __restrict__ nei,
                                                    const float* __restrict__ wr,
                                                    const float* __restrict__ wi) {
    int io2 = blockIdx.x * 256 + threadIdx.x;
    int io = io2 * 2;
    int vstart = blockIdx.y * WVB;
    int vcnt = min(WVB, VV - vstart);
    float s = g_inv_norm;
    float2 P0r[16], P0i[16], P1r[16], P1i[16];
#pragma unroll
    for (int d = 0; d < 16; d++) {
        float2 r0 = *(const float2*)&wr[(d * 3 + 0) * 4096 + io];
        float2 r1 = *(const float2*)&wr[(d * 3 + 1) * 4096 + io];
        float2 r2 = *(const float2*)&wr[(d * 3 + 2) * 4096 + io];
        float2 i0 = *(const float2*)&wi[(d * 3 + 0) * 4096 + io];
        float2 i1 = *(const float2*)&wi[(d * 3 + 1) * 4096 + io];
        float2 i2 = *(const float2*)&wi[(d * 3 + 2) * 4096 + io];
        P0r[d] = make_float2(r0.x - r2.x, r0.y - r2.y);
        P0i[d] = make_float2(i0.x - i2.x, i0.y - i2.y);
        P1r[d] = make_float2((r1.x + 2.f * r2.x) * s, (r1.y + 2.f * r2.y) * s);
        P1i[d] = make_float2((i1.x + 2.f * i2.x) * s, (i1.y + 2.f * i2.y) * s);
    }
    __shared__ float2 nsm[WVB * 16];
    for (int t = threadIdx.x; t < vcnt * 16; t += 256)
        nsm[t] = make_float2(ner[vstart * 16 + t], nei[vstart * 16 + t]);
    __syncthreads();
    for (int vl = 0; vl < vcnt; vl++) {
        float Ar0 = 0.f, Ai0 = 0.f, Cr0 = 0.f, Ci0 = 0.f;
        float Ar1 = 0.f, Ai1 = 0.f, Cr1 = 0.f, Ci1 = 0.f;
#pragma unroll
        for (int d = 0; d < 16; d++) {
            float2 n = nsm[vl * 16 + d];
            float a = n.x, b = n.y;
            Ar0 += a * P0r[d].x - b * P0i[d].x;
            Ai0 += a * P0i[d].x + b * P0r[d].x;
            Cr0 += a * P1r[d].x - b * P1i[d].x;
            Ci0 += a * P1i[d].x + b * P1r[d].x;
            Ar1 += a * P0r[d].y - b * P0i[d].y;
            Ai1 += a * P0i[d].y + b * P0r[d].y;
            Cr1 += a * P1r[d].y - b * P1i[d].y;
            Ci1 += a * P1i[d].y + b * P1r[d].y;
        }
        size_t off = (size_t)(vstart + vl) * 4096 + io;
        g_AC4[off]     = make_float4(Ar0, Ai0, Cr0, Ci0);
        g_AC4[off + 1] = make_float4(Ar1, Ai1, Cr1, Ci1);
    }
}

// ================ K4: HMMA out — D(128x64) = W(128x192) @ X(64x192)^T ================
// mma.sync.m16n8k16 bf16, hi/lo 3-pass split. Row-major smem tiles, row stride 100 words
// (100 mod 32 = 4 -> all fragment LDS.32 conflict-free).
#define SW 100
#define SM_WH 0                       // 128*400 B = 51200
#define SM_WL 51200
#define SM_XH 102400                  // 64*400 B = 25600
#define SM_XL 128000
#define SM_BIAS 153600                // 128 floats
#define SM_TOTAL 154112

__device__ __forceinline__ void split_pack(float v0, float v1, uint32_t& hi, uint32_t& lo) {
    __nv_bfloat16 h0 = __float2bfloat16_rn(v0);
    __nv_bfloat16 h1 = __float2bfloat16_rn(v1);
    __nv_bfloat16 l0 = __float2bfloat16_rn(v0 - __bfloat162float(h0));
    __nv_bfloat16 l1 = __float2bfloat16_rn(v1 - __bfloat162float(h1));
    __nv_bfloat162 hp = __nv_bfloat162(h0, h1), lp = __nv_bfloat162(l0, l1);
    hi = *(uint32_t*)&hp;
    lo = *(uint32_t*)&lp;
}

__device__ __forceinline__ void hmma(float* d, const uint32_t* a, uint32_t b0, uint32_t b1) {
    asm volatile(
        "mma.sync.aligned.m16n8k16.row.col.f32.bf16.bf16.f32 "
        "{%0,%1,%2,%3}, {%4,%5,%6,%7}, {%8,%9}, {%0,%1,%2,%3};"
        : "+f"(d[0]), "+f"(d[1]), "+f"(d[2]), "+f"(d[3])
        : "r"(a[0]), "r"(a[1]), "r"(a[2]), "r"(a[3]), "r"(b0), "r"(b1));
}

__global__ void __launch_bounds__(256) out_mma(const float* __restrict__ x,
                                               const float* __restrict__ ner,
                                               const float* __restrict__ nei,
                                               const float* __restrict__ bre,
                                               const float* __restrict__ bim,
                                               float* __restrict__ out) {
    extern __shared__ char smc[];
    uint32_t* wh = (uint32_t*)(smc + SM_WH);
    uint32_t* wl = (uint32_t*)(smc + SM_WL);
    uint32_t* xh = (uint32_t*)(smc + SM_XH);
    uint32_t* xl = (uint32_t*)(smc + SM_XL);
    float* bias = (float*)(smc + SM_BIAS);

    int tid = threadIdx.x;
    int wid = tid >> 5, lane = tid & 31;
    int v = blockIdx.x;

    // ---- fill W tiles: rows n=2o (re: Ar|Cr|-Ci), n=2o+1 (im: Ai|Ci|Cr) ----
    {
        const float4* ac = g_AC4 + (size_t)v * 4096;
#pragma unroll
        for (int it = 0; it < 8; it++) {
            int idx = tid + it * 256;
            int p = idx >> 6;           // i-pair 0..31 (k word)
            int o = idx & 63;
            int i0 = p * 2;
            float4 c0 = ac[i0 * 64 + o];
            float4 c1 = ac[(i0 + 1) * 64 + o];
            uint32_t r0 = (2 * o) * SW + p;
            uint32_t r1 = (2 * o + 1) * SW + p;
            uint32_t hi, lo;
            split_pack(c0.x, c1.x, hi, lo);   wh[r0]      = hi; wl[r0]      = lo;  // Ar @ k=i
            split_pack(c0.z, c1.z, hi, lo);   wh[r0 + 32] = hi; wl[r0 + 32] = lo;  // Cr @ k=64+i
            split_pack(-c0.w, -c1.w, hi, lo); wh[r0 + 64] = hi; wl[r0 + 64] = lo;  // -Ci @ k=128+i
            split_pack(c0.y, c1.y, hi, lo);   wh[r1]      = hi; wl[r1]      = lo;  // Ai
            split_pack(c0.w, c1.w, hi, lo);   wh[r1 + 32] = hi; wl[r1 + 32] = lo;  // Ci
            split_pack(c0.z, c1.z, hi, lo);   wh[r1 + 64] = hi; wl[r1 + 64] = lo;  // Cr
        }
    }
    // ---- fill X tiles: rows = batch b, k = [x | yr | yi] ----
#pragma unroll
    for (int it = 0; it < 8; it++) {
        int idx = tid + it * 256;
        int b = idx >> 5;
        int p = idx & 31;
        int i0 = p * 2;
        size_t go = ((size_t)b * VV + v) * 64 + i0;
        float2 xv = *(const float2*)&x[go];
        float4 yv = *(const float4*)&g_y[go];   // (yr0, yi0, yr1, yi1)
        uint32_t r = b * SW + p;
        uint32_t hi, lo;
        split_pack(xv.x, xv.y, hi, lo); xh[r]      = hi; xl[r]      = lo;
        split_pack(yv.x, yv.z, hi, lo); xh[r + 32] = hi; xl[r + 32] = lo;
        split_pack(yv.y, yv.w, hi, lo); xh[r + 64] = hi; xl[r + 64] = lo;
    }
    // ---- bias[m], m = 2o+reim ----
    if (tid < 128) {
        int o = tid >> 1, rei = tid & 1;
        float re = 0.f, im = 0.f;
#pragma unroll
        for (int d = 0; d < 16; d++) {
            float a = ner[v * 16 + d], b2 = nei[v * 16 + d];
            float pr = bre[d * 64 + o], pi = bim[d * 64 + o];
            re += a * pr - b2 * pi;
            im += a * pi + b2 * pr;
        }
        bias[tid] = rei ? im : re;
    }
    __syncthreads();

    // ---- compute: warp owns m-tile [wid*16, wid*16+16) x full N=64 ----
    int gid = lane >> 2, tig = lane & 3;
    int m0 = wid * 16;
    float acc[8][4] = {};

    for (int kc = 0; kc < 12; kc++) {
        int ka = kc * 8 + tig;
        uint32_t ah[4], al[4];
        int rlo = (m0 + gid) * SW + ka;
        int rhi = (m0 + gid + 8) * SW + ka;
        ah[0] = wh[rlo];     ah[1] = wh[rhi];
        ah[2] = wh[rlo + 4]; ah[3] = wh[rhi + 4];
        al[0] = wl[rlo];     al[1] = wl[rhi];
        al[2] = wl[rlo + 4]; al[3] = wl[rhi + 4];
#pragma unroll
        for (int nt = 0; nt < 8; nt++) {
            int rb = (nt * 8 + gid) * SW + ka;
            uint32_t bh0 = xh[rb], bh1 = xh[rb + 4];
            uint32_t bl0 = xl[rb], bl1 = xl[rb + 4];
            hmma(acc[nt], ah, bh0, bh1);
            hmma(acc[nt], al, bh0, bh1);
            hmma(acc[nt], ah, bl0, bl1);
        }
    }

    // ---- epilogue: D(gid row, 2*tig col) mapping; add bias; store ----
    int m_lo = m0 + gid, m_hi = m0 + gid + 8;
    float b_lo = bias[m_lo], b_hi = bias[m_hi];
#pragma unroll
    for (int nt = 0; nt < 8; nt++) {
        int b0 = nt * 8 + 2 * tig;
        size_t o00 = ((size_t)b0 * VV + v) * 128;
        size_t o01 = ((size_t)(b0 + 1) * VV + v) * 128;
        out[o00 + m_lo] = acc[nt][0] + b_lo;
        out[o01 + m_lo] = acc[nt][1] + b_lo;
        out[o00 + m_hi] = acc[nt][2] + b_hi;
        out[o01 + m_hi] = acc[nt][3] + b_hi;
    }
}

extern "C" void kernel_launch(void* const* d_in, const int* in_sizes, int n_in,
                              void* d_out, int out_size) {
    const float* x   = (const float*)d_in[0];
    const float* ner = (const float*)d_in[1];
    const float* nei = (const float*)d_in[2];
    const float* wr  = (const float*)d_in[3];
    const float* wi  = (const float*)d_in[4];
    const float* bre = (const float*)d_in[5];
    const float* bim = (const float*)d_in[6];
    float* out = (float*)d_out;

    cudaFuncSetAttribute(out_mma, cudaFuncAttributeMaxDynamicSharedMemorySize, SM_TOTAL);

    k1_gram_z<<<32 + 2 * BB, 256>>>(x, ner, nei);             // L1
    k2_reduce_y<<<1 + BB * 32, 256>>>(ner, nei);              // L2
    wcomb_kernel<<<dim3(8, 56), 256>>>(ner, nei, wr, wi);     // L3
    out_mma<<<VV, 256, SM_TOTAL>>>(x, ner, nei, bre, bim, out);  // L4 (ncu target)
}

// round 13
// speedup vs baseline: 2.0388x; 1.0150x over previous
#include <cuda_runtime.h>
#include <cuda_bf16.h>
#include <cstdint>

#define BB 64
#define VV 2000
#define DD 16
#define CI 64
#define CO 64
#define VHALF 1000
#define VTILE 128
#define WVB 36

// ---------------- scratch ----------------
__device__ float g_partG[32 * 512];
__device__ float g_inv_norm;
__device__ float g_Zre[2 * BB * DD * CI];
__device__ float g_Zim[2 * BB * DD * CI];
__device__ float2 g_y[(size_t)BB * VV * CI];
__device__ float4 g_AC4[(size_t)VV * CI * CO];   // (Ar, Ai, Cr, Ci)

// ================ K1: gram_partial + z (unchanged, proven) ================
__global__ void __launch_bounds__(256) k1_gram_z(const float* __restrict__ x,
                                                 const float* __restrict__ ner,
                                                 const float* __restrict__ nei) {
    __shared__ float xs[VTILE * 64];
    __shared__ float2 ns[VTILE * 16];
    if (blockIdx.x < 32) {
        float* sr = xs;
        float* si = xs + 1024;
        int blk = blockIdx.x;
        int v0 = blk * 63;
        int cnt = min(63, VV - v0);
        for (int t = threadIdx.x; t < cnt * 16; t += 256) {
            sr[t] = ner[v0 * 16 + t];
            si[t] = nei[v0 * 16 + t];
        }
        __syncthreads();
        int d = threadIdx.x >> 4, e = threadIdx.x & 15;
        float ar = 0.f, ai = 0.f;
        for (int vv = 0; vv < cnt; vv++) {
            float a = sr[vv * 16 + d], b = si[vv * 16 + d];
            float c = sr[vv * 16 + e], dd = si[vv * 16 + e];
            ar += a * c + b * dd;
            ai += a * dd - b * c;
        }
        g_partG[blk * 512 + threadIdx.x * 2]     = ar;
        g_partG[blk * 512 + threadIdx.x * 2 + 1] = ai;
    } else {
        int bx = blockIdx.x - 32;
        int b = bx >> 1;
        int half = bx & 1;
        int vbase = half * VHALF;
        int ig = threadIdx.x & 63;
        int dg = threadIdx.x >> 6;
        float ar[4] = {}, ai[4] = {};
        for (int v0 = 0; v0 < VHALF; v0 += VTILE) {
            int cnt = min(VTILE, VHALF - v0);
            __syncthreads();
            {
                const float4* src = (const float4*)(x + (size_t)b * VV * 64 + (size_t)(vbase + v0) * 64);
                float4* dst = (float4*)xs;
                for (int t = threadIdx.x; t < cnt * 16; t += 256) dst[t] = src[t];
            }
            for (int t = threadIdx.x; t < cnt * 16; t += 256) {
                int vv = t >> 4, d = t & 15;
                ns[vv * 16 + d] = make_float2(ner[(vbase + v0 + vv) * 16 + d],
                                              nei[(vbase + v0 + vv) * 16 + d]);
            }
            __syncthreads();
#pragma unroll 4
            for (int vv = 0; vv < cnt; vv++) {
                float xv = xs[vv * 64 + ig];
                float2 n0 = ns[vv * 16 + dg * 4 + 0];
                float2 n1 = ns[vv * 16 + dg * 4 + 1];
                float2 n2 = ns[vv * 16 + dg * 4 + 2];
                float2 n3 = ns[vv * 16 + dg * 4 + 3];
                ar[0] += n0.x * xv; ai[0] -= n0.y * xv;
                ar[1] += n1.x * xv; ai[1] -= n1.y * xv;
                ar[2] += n2.x * xv; ai[2] -= n2.y * xv;
                ar[3] += n3.x * xv; ai[3] -= n3.y * xv;
            }
        }
#pragma unroll
        for (int k = 0; k < 4; k++) {
            int idx = ((half * BB + b) * 16 + dg * 4 + k) * 64 + ig;
            g_Zre[idx] = ar[k];
            g_Zim[idx] = ai[k];
        }
    }
}

// ================ K2: gram_reduce + y (unchanged) ================
__global__ void __launch_bounds__(256) k2_reduce_y(const float* __restrict__ ner,
                                                   const float* __restrict__ nei) {
    __shared__ float sm[4096];
    if (blockIdx.x == 0) {
        float* red = sm;
        int t = threadIdx.x;
        float gr = 0.f, gi = 0.f;
        for (int blk = 0; blk < 32; blk++) {
            gr += g_partG[blk * 512 + t * 2];
            gi += g_partG[blk * 512 + t * 2 + 1];
        }
        red[t] = gr * gr + gi * gi;
        __syncthreads();
        for (int s = 128; s > 0; s >>= 1) {
            if (t < s) red[t] += red[t + s];
            __syncthreads();
        }
        if (t == 0) g_inv_norm = rsqrtf(red[0]);
    } else {
        float* Zr = sm;
        float* Zi = sm + 1024;
        float* nr = sm + 2048;
        float* ni = sm + 3072;
        int bx = blockIdx.x - 1;
        int b = bx >> 5;
        int v0 = (bx & 31) * 64;
        int vcnt = min(64, VV - v0);
        for (int t = threadIdx.x; t < 1024; t += 256) {
            Zr[t] = g_Zre[b * 1024 + t] + g_Zre[65536 + b * 1024 + t];
            Zi[t] = g_Zim[b * 1024 + t] + g_Zim[65536 + b * 1024 + t];
        }
        for (int t = threadIdx.x; t < vcnt * 16; t += 256) {
            nr[t] = ner[v0 * 16 + t];
            ni[t] = nei[v0 * 16 + t];
        }
        __syncthreads();
        int i = threadIdx.x & 63;
        int vb = threadIdx.x >> 6;
        float zr[16], zi[16];
#pragma unroll
        for (int d = 0; d < 16; d++) { zr[d] = Zr[d * 64 + i]; zi[d] = Zi[d * 64 + i]; }
        for (int vl = vb; vl < vcnt; vl += 4) {
            float yr = 0.f, yi = 0.f;
#pragma unroll
            for (int d = 0; d < 16; d++) {
                float a = nr[vl * 16 + d], c = ni[vl * 16 + d];
                yr += a * zr[d] - c * zi[d];
                yi += a * zi[d] + c * zr[d];
            }
            g_y[(size_t)b * VV * 64 + (size_t)(v0 + vl) * 64 + i] = make_float2(yr, yi);
        }
    }
}

// ================ K3: wcomb (unchanged) ================
__global__ void __launch_bounds__(256) wcomb_kernel(const float* __restrict__ ner,
                                                    const float* __restrict__ nei,
                                                    const float* __restrict__ wr,
                                                    const float* __restrict__ wi) {
    int io2 = blockIdx.x * 256 + threadIdx.x;
    int io = io2 * 2;
    int vstart = blockIdx.y * WVB;
    int vcnt = min(WVB, VV - vstart);
    float s = g_inv_norm;
    float2 P0r[16], P0i[16], P1r[16], P1i[16];
#pragma unroll
    for (int d = 0; d < 16; d++) {
        float2 r0 = *(const float2*)&wr[(d * 3 + 0) * 4096 + io];
        float2 r1 = *(const float2*)&wr[(d * 3 + 1) * 4096 + io];
        float2 r2 = *(const float2*)&wr[(d * 3 + 2) * 4096 + io];
        float2 i0 = *(const float2*)&wi[(d * 3 + 0) * 4096 + io];
        float2 i1 = *(const float2*)&wi[(d * 3 + 1) * 4096 + io];
        float2 i2 = *(const float2*)&wi[(d * 3 + 2) * 4096 + io];
        P0r[d] = make_float2(r0.x - r2.x, r0.y - r2.y);
        P0i[d] = make_float2(i0.x - i2.x, i0.y - i2.y);
        P1r[d] = make_float2((r1.x + 2.f * r2.x) * s, (r1.y + 2.f * r2.y) * s);
        P1i[d] = make_float2((i1.x + 2.f * i2.x) * s, (i1.y + 2.f * i2.y) * s);
    }
    __shared__ float2 nsm[WVB * 16];
    for (int t = threadIdx.x; t < vcnt * 16; t += 256)
        nsm[t] = make_float2(ner[vstart * 16 + t], nei[vstart * 16 + t]);
    __syncthreads();
    for (int vl = 0; vl < vcnt; vl++) {
        float Ar0 = 0.f, Ai0 = 0.f, Cr0 = 0.f, Ci0 = 0.f;
        float Ar1 = 0.f, Ai1 = 0.f, Cr1 = 0.f, Ci1 = 0.f;
#pragma unroll
        for (int d = 0; d < 16; d++) {
            float2 n = nsm[vl * 16 + d];
            float a = n.x, b = n.y;
            Ar0 += a * P0r[d].x - b * P0i[d].x;
            Ai0 += a * P0i[d].x + b * P0r[d].x;
            Cr0 += a * P1r[d].x - b * P1i[d].x;
            Ci0 += a * P1i[d].x + b * P1r[d].x;
            Ar1 += a * P0r[d].y - b * P0i[d].y;
            Ai1 += a * P0i[d].y + b * P0r[d].y;
            Cr1 += a * P1r[d].y - b * P1i[d].y;
            Ci1 += a * P1i[d].y + b * P1r[d].y;
        }
        size_t off = (size_t)(vstart + vl) * 4096 + io;
        g_AC4[off]     = make_float4(Ar0, Ai0, Cr0, Ci0);
        g_AC4[off + 1] = make_float4(Ar1, Ai1, Cr1, Ci1);
    }
}

// ================ K4: HMMA out, o-half blocks (2 blocks/SM) ================
// Block (oh, v): D_local(64x64) = W_half(64x192) @ X(64x192)^T
// 8 warps tiled 4(m) x 2(n): warp = 16 m-rows x 32 n-cols.
#define SW 100
#define SM_WH 0                       // 64*100*4 = 25600
#define SM_WL 25600
#define SM_XH 51200
#define SM_XL 76800
#define SM_BIAS 102400                // 64 floats
#define SM_TOTAL 102656

__device__ __forceinline__ void split_pack(float v0, float v1, uint32_t& hi, uint32_t& lo) {
    __nv_bfloat16 h0 = __float2bfloat16_rn(v0);
    __nv_bfloat16 h1 = __float2bfloat16_rn(v1);
    __nv_bfloat16 l0 = __float2bfloat16_rn(v0 - __bfloat162float(h0));
    __nv_bfloat16 l1 = __float2bfloat16_rn(v1 - __bfloat162float(h1));
    __nv_bfloat162 hp = __nv_bfloat162(h0, h1), lp = __nv_bfloat162(l0, l1);
    hi = *(uint32_t*)&hp;
    lo = *(uint32_t*)&lp;
}

__device__ __forceinline__ void hmma(float* d, const uint32_t* a, uint32_t b0, uint32_t b1) {
    asm volatile(
        "mma.sync.aligned.m16n8k16.row.col.f32.bf16.bf16.f32 "
        "{%0,%1,%2,%3}, {%4,%5,%6,%7}, {%8,%9}, {%0,%1,%2,%3};"
        : "+f"(d[0]), "+f"(d[1]), "+f"(d[2]), "+f"(d[3])
        : "r"(a[0]), "r"(a[1]), "r"(a[2]), "r"(a[3]), "r"(b0), "r"(b1));
}

__global__ void __launch_bounds__(256) out_mma(const float* __restrict__ x,
                                               const float* __restrict__ ner,
                                               const float* __restrict__ nei,
                                               const float* __restrict__ bre,
                                               const float* __restrict__ bim,
                                               float* __restrict__ out) {
    extern __shared__ char smc[];
    uint32_t* wh = (uint32_t*)(smc + SM_WH);
    uint32_t* wl = (uint32_t*)(smc + SM_WL);
    uint32_t* xh = (uint32_t*)(smc + SM_XH);
    uint32_t* xl = (uint32_t*)(smc + SM_XL);
    float* bias = (float*)(smc + SM_BIAS);

    int tid = threadIdx.x;
    int wid = tid >> 5, lane = tid & 31;
    int oh = blockIdx.x;     // o-half
    int v = blockIdx.y;

    // ---- fill W half: local rows n = 2*ol (re) / 2*ol+1 (im), o = oh*32 + ol ----
    {
        const float4* ac = g_AC4 + (size_t)v * 4096 + oh * 32;
#pragma unroll
        for (int it = 0; it < 4; it++) {
            int idx = tid + it * 256;       // 1024 items: p(0..31) x ol(0..31)
            int p = idx >> 5;               // i-pair
            int ol = idx & 31;
            int i0 = p * 2;
            float4 c0 = ac[i0 * 64 + ol];
            float4 c1 = ac[(i0 + 1) * 64 + ol];
            uint32_t r0 = (2 * ol) * SW + p;
            uint32_t r1 = (2 * ol + 1) * SW + p;
            uint32_t hi, lo;
            split_pack(c0.x, c1.x, hi, lo);   wh[r0]      = hi; wl[r0]      = lo;  // Ar
            split_pack(c0.z, c1.z, hi, lo);   wh[r0 + 32] = hi; wl[r0 + 32] = lo;  // Cr
            split_pack(-c0.w, -c1.w, hi, lo); wh[r0 + 64] = hi; wl[r0 + 64] = lo;  // -Ci
            split_pack(c0.y, c1.y, hi, lo);   wh[r1]      = hi; wl[r1]      = lo;  // Ai
            split_pack(c0.w, c1.w, hi, lo);   wh[r1 + 32] = hi; wl[r1 + 32] = lo;  // Ci
            split_pack(c0.z, c1.z, hi, lo);   wh[r1 + 64] = hi; wl[r1 + 64] = lo;  // Cr
        }
    }
    // ---- fill X (full): rows = batch, k = [x | yr | yi] ----
#pragma unroll
    for (int it = 0; it < 8; it++) {
        int idx = tid + it * 256;
        int b = idx >> 5;
        int p = idx & 31;
        int i0 = p * 2;
        size_t go = ((size_t)b * VV + v) * 64 + i0;
        float2 xv = *(const float2*)&x[go];
        float4 yv = *(const float4*)&g_y[go];
        uint32_t r = b * SW + p;
        uint32_t hi, lo;
        split_pack(xv.x, xv.y, hi, lo); xh[r]      = hi; xl[r]      = lo;
        split_pack(yv.x, yv.z, hi, lo); xh[r + 32] = hi; xl[r + 32] = lo;
        split_pack(yv.y, yv.w, hi, lo); xh[r + 64] = hi; xl[r + 64] = lo;
    }
    // ---- bias for the 64 local rows: m = 2*ol + reim, o = oh*32 + ol ----
    if (tid < 64) {
        int ol = tid >> 1, rei = tid & 1;
        int o = oh * 32 + ol;
        float re = 0.f, im = 0.f;
#pragma unroll
        for (int d = 0; d < 16; d++) {
            float a = ner[v * 16 + d], b2 = nei[v * 16 + d];
            float pr = bre[d * 64 + o], pi = bim[d * 64 + o];
            re += a * pr - b2 * pi;
            im += a * pi + b2 * pr;
        }
        bias[tid] = rei ? im : re;
    }
    __syncthreads();

    // ---- compute: warp (mt, nh) = 16 m-rows x 32 n-cols ----
    int gid = lane >> 2, tig = lane & 3;
    int mt = wid & 3, nh = wid >> 2;
    int m0 = mt * 16;
    float acc[4][4] = {};

    for (int kc = 0; kc < 12; kc++) {
        int ka = kc * 8 + tig;
        uint32_t ah[4], al[4];
        int rlo = (m0 + gid) * SW + ka;
        int rhi = rlo + 8 * SW;
        ah[0] = wh[rlo];     ah[1] = wh[rhi];
        ah[2] = wh[rlo + 4]; ah[3] = wh[rhi + 4];
        al[0] = wl[rlo];     al[1] = wl[rhi];
        al[2] = wl[rlo + 4]; al[3] = wl[rhi + 4];
#pragma unroll
        for (int nt = 0; nt < 4; nt++) {
            int rb = (nh * 32 + nt * 8 + gid) * SW + ka;
            uint32_t bh0 = xh[rb], bh1 = xh[rb + 4];
            uint32_t bl0 = xl[rb], bl1 = xl[rb + 4];
            hmma(acc[nt], ah, bh0, bh1);
            hmma(acc[nt], al, bh0, bh1);
            hmma(acc[nt], ah, bl0, bl1);
        }
    }

    // ---- epilogue ----
    int m_lo = m0 + gid, m_hi = m0 + gid + 8;
    float b_lo = bias[m_lo], b_hi = bias[m_hi];
    int ng_lo = oh * 64 + m_lo, ng_hi = oh * 64 + m_hi;
#pragma unroll
    for (int nt = 0; nt < 4; nt++) {
        int b0 = nh * 32 + nt * 8 + 2 * tig;
        size_t o00 = ((size_t)b0 * VV + v) * 128;
        size_t o01 = ((size_t)(b0 + 1) * VV + v) * 128;
        out[o00 + ng_lo] = acc[nt][0] + b_lo;
        out[o01 + ng_lo] = acc[nt][1] + b_lo;
        out[o00 + ng_hi] = acc[nt][2] + b_hi;
        out[o01 + ng_hi] = acc[nt][3] + b_hi;
    }
}

extern "C" void kernel_launch(void* const* d_in, const int* in_sizes, int n_in,
                              void* d_out, int out_size) {
    const float* x   = (const float*)d_in[0];
    const float* ner = (const float*)d_in[1];
    const float* nei = (const float*)d_in[2];
    const float* wr  = (const float*)d_in[3];
    const float* wi  = (const float*)d_in[4];
    const float* bre = (const float*)d_in[5];
    const float* bim = (const float*)d_in[6];
    float* out = (float*)d_out;

    cudaFuncSetAttribute(out_mma, cudaFuncAttributeMaxDynamicSharedMemorySize, SM_TOTAL);

    k1_gram_z<<<32 + 2 * BB, 256>>>(x, ner, nei);             // L1
    k2_reduce_y<<<1 + BB * 32, 256>>>(ner, nei);              // L2
    wcomb_kernel<<<dim3(8, 56), 256>>>(ner, nei, wr, wi);     // L3
    out_mma<<<dim3(2, VV), 256, SM_TOTAL>>>(x, ner, nei, bre, bim, out);  // L4 (ncu target)
}

// round 14
// speedup vs baseline: 2.0515x; 1.0062x over previous
#include <cuda_runtime.h>
#include <cuda_bf16.h>
#include <cstdint>

#define BB 64
#define VV 2000
#define DD 16
#define CI 64
#define CO 64
#define VHALF 1000
#define VTILE 128
#define WVB 36

// ---------------- scratch ----------------
__device__ float g_partG[32 * 512];
__device__ float g_inv_norm;
__device__ float g_Zre[2 * BB * DD * CI];
__device__ float g_Zim[2 * BB * DD * CI];
__device__ float2 g_y[(size_t)BB * VV * CI];
__device__ float4 g_AC4[(size_t)VV * CI * CO];   // (Ar, Ai, Cr, Ci)

// ================ K1: gram_partial + z (unchanged, proven) ================
__global__ void __launch_bounds__(256) k1_gram_z(const float* __restrict__ x,
                                                 const float* __restrict__ ner,
                                                 const float* __restrict__ nei) {
    __shared__ float xs[VTILE * 64];
    __shared__ float2 ns[VTILE * 16];
    if (blockIdx.x < 32) {
        float* sr = xs;
        float* si = xs + 1024;
        int blk = blockIdx.x;
        int v0 = blk * 63;
        int cnt = min(63, VV - v0);
        for (int t = threadIdx.x; t < cnt * 16; t += 256) {
            sr[t] = ner[v0 * 16 + t];
            si[t] = nei[v0 * 16 + t];
        }
        __syncthreads();
        int d = threadIdx.x >> 4, e = threadIdx.x & 15;
        float ar = 0.f, ai = 0.f;
        for (int vv = 0; vv < cnt; vv++) {
            float a = sr[vv * 16 + d], b = si[vv * 16 + d];
            float c = sr[vv * 16 + e], dd = si[vv * 16 + e];
            ar += a * c + b * dd;
            ai += a * dd - b * c;
        }
        g_partG[blk * 512 + threadIdx.x * 2]     = ar;
        g_partG[blk * 512 + threadIdx.x * 2 + 1] = ai;
    } else {
        int bx = blockIdx.x - 32;
        int b = bx >> 1;
        int half = bx & 1;
        int vbase = half * VHALF;
        int ig = threadIdx.x & 63;
        int dg = threadIdx.x >> 6;
        float ar[4] = {}, ai[4] = {};
        for (int v0 = 0; v0 < VHALF; v0 += VTILE) {
            int cnt = min(VTILE, VHALF - v0);
            __syncthreads();
            {
                const float4* src = (const float4*)(x + (size_t)b * VV * 64 + (size_t)(vbase + v0) * 64);
                float4* dst = (float4*)xs;
                for (int t = threadIdx.x; t < cnt * 16; t += 256) dst[t] = src[t];
            }
            for (int t = threadIdx.x; t < cnt * 16; t += 256) {
                int vv = t >> 4, d = t & 15;
                ns[vv * 16 + d] = make_float2(ner[(vbase + v0 + vv) * 16 + d],
                                              nei[(vbase + v0 + vv) * 16 + d]);
            }
            __syncthreads();
#pragma unroll 4
            for (int vv = 0; vv < cnt; vv++) {
                float xv = xs[vv * 64 + ig];
                float2 n0 = ns[vv * 16 + dg * 4 + 0];
                float2 n1 = ns[vv * 16 + dg * 4 + 1];
                float2 n2 = ns[vv * 16 + dg * 4 + 2];
                float2 n3 = ns[vv * 16 + dg * 4 + 3];
                ar[0] += n0.x * xv; ai[0] -= n0.y * xv;
                ar[1] += n1.x * xv; ai[1] -= n1.y * xv;
                ar[2] += n2.x * xv; ai[2] -= n2.y * xv;
                ar[3] += n3.x * xv; ai[3] -= n3.y * xv;
            }
        }
#pragma unroll
        for (int k = 0; k < 4; k++) {
            int idx = ((half * BB + b) * 16 + dg * 4 + k) * 64 + ig;
            g_Zre[idx] = ar[k];
            g_Zim[idx] = ai[k];
        }
    }
}

// ================ K2: gram_reduce + y (unchanged) ================
__global__ void __launch_bounds__(256) k2_reduce_y(const float* __restrict__ ner,
                                                   const float* __restrict__ nei) {
    __shared__ float sm[4096];
    if (blockIdx.x == 0) {
        float* red = sm;
        int t = threadIdx.x;
        float gr = 0.f, gi = 0.f;
        for (int blk = 0; blk < 32; blk++) {
            gr += g_partG[blk * 512 + t * 2];
            gi += g_partG[blk * 512 + t * 2 + 1];
        }
        red[t] = gr * gr + gi * gi;
        __syncthreads();
        for (int s = 128; s > 0; s >>= 1) {
            if (t < s) red[t] += red[t + s];
            __syncthreads();
        }
        if (t == 0) g_inv_norm = rsqrtf(red[0]);
    } else {
        float* Zr = sm;
        float* Zi = sm + 1024;
        float* nr = sm + 2048;
        float* ni = sm + 3072;
        int bx = blockIdx.x - 1;
        int b = bx >> 5;
        int v0 = (bx & 31) * 64;
        int vcnt = min(64, VV - v0);
        for (int t = threadIdx.x; t < 1024; t += 256) {
            Zr[t] = g_Zre[b * 1024 + t] + g_Zre[65536 + b * 1024 + t];
            Zi[t] = g_Zim[b * 1024 + t] + g_Zim[65536 + b * 1024 + t];
        }
        for (int t = threadIdx.x; t < vcnt * 16; t += 256) {
            nr[t] = ner[v0 * 16 + t];
            ni[t] = nei[v0 * 16 + t];
        }
        __syncthreads();
        int i = threadIdx.x & 63;
        int vb = threadIdx.x >> 6;
        float zr[16], zi[16];
#pragma unroll
        for (int d = 0; d < 16; d++) { zr[d] = Zr[d * 64 + i]; zi[d] = Zi[d * 64 + i]; }
        for (int vl = vb; vl < vcnt; vl += 4) {
            float yr = 0.f, yi = 0.f;
#pragma unroll
            for (int d = 0; d < 16; d++) {
                float a = nr[vl * 16 + d], c = ni[vl * 16 + d];
                yr += a * zr[d] - c * zi[d];
                yi += a * zi[d] + c * zr[d];
            }
            g_y[(size_t)b * VV * 64 + (size_t)(v0 + vl) * 64 + i] = make_float2(yr, yi);
        }
    }
}

// ================ K3: wcomb (unchanged) ================
__global__ void __launch_bounds__(256) wcomb_kernel(const float* __restrict__ ner,
                                                    const float* __restrict__ nei,
                                                    const float* __restrict__ wr,
                                                    const float* __restrict__ wi) {
    int io2 = blockIdx.x * 256 + threadIdx.x;
    int io = io2 * 2;
    int vstart = blockIdx.y * WVB;
    int vcnt = min(WVB, VV - vstart);
    float s = g_inv_norm;
    float2 P0r[16], P0i[16], P1r[16], P1i[16];
#pragma unroll
    for (int d = 0; d < 16; d++) {
        float2 r0 = *(const float2*)&wr[(d * 3 + 0) * 4096 + io];
        float2 r1 = *(const float2*)&wr[(d * 3 + 1) * 4096 + io];
        float2 r2 = *(const float2*)&wr[(d * 3 + 2) * 4096 + io];
        float2 i0 = *(const float2*)&wi[(d * 3 + 0) * 4096 + io];
        float2 i1 = *(const float2*)&wi[(d * 3 + 1) * 4096 + io];
        float2 i2 = *(const float2*)&wi[(d * 3 + 2) * 4096 + io];
        P0r[d] = make_float2(r0.x - r2.x, r0.y - r2.y);
        P0i[d] = make_float2(i0.x - i2.x, i0.y - i2.y);
        P1r[d] = make_float2((r1.x + 2.f * r2.x) * s, (r1.y + 2.f * r2.y) * s);
        P1i[d] = make_float2((i1.x + 2.f * i2.x) * s, (i1.y + 2.f * i2.y) * s);
    }
    __shared__ float2 nsm[WVB * 16];
    for (int t = threadIdx.x; t < vcnt * 16; t += 256)
        nsm[t] = make_float2(ner[vstart * 16 + t], nei[vstart * 16 + t]);
    __syncthreads();
    for (int vl = 0; vl < vcnt; vl++) {
        float Ar0 = 0.f, Ai0 = 0.f, Cr0 = 0.f, Ci0 = 0.f;
        float Ar1 = 0.f, Ai1 = 0.f, Cr1 = 0.f, Ci1 = 0.f;
#pragma unroll
        for (int d = 0; d < 16; d++) {
            float2 n = nsm[vl * 16 + d];
            float a = n.x, b = n.y;
            Ar0 += a * P0r[d].x - b * P0i[d].x;
            Ai0 += a * P0i[d].x + b * P0r[d].x;
            Cr0 += a * P1r[d].x - b * P1i[d].x;
            Ci0 += a * P1i[d].x + b * P1r[d].x;
            Ar1 += a * P0r[d].y - b * P0i[d].y;
            Ai1 += a * P0i[d].y + b * P0r[d].y;
            Cr1 += a * P1r[d].y - b * P1i[d].y;
            Ci1 += a * P1i[d].y + b * P1r[d].y;
        }
        size_t off = (size_t)(vstart + vl) * 4096 + io;
        g_AC4[off]     = make_float4(Ar0, Ai0, Cr0, Ci0);
        g_AC4[off + 1] = make_float4(Ar1, Ai1, Cr1, Ci1);
    }
}

// ================ K4: HMMA out, o-half blocks, split accumulators ================
#define SW 100
#define SM_WH 0
#define SM_WL 25600
#define SM_XH 51200
#define SM_XL 76800
#define SM_BIAS 102400
#define SM_TOTAL 102656

__device__ __forceinline__ void split_pack(float v0, float v1, uint32_t& hi, uint32_t& lo) {
    __nv_bfloat16 h0 = __float2bfloat16_rn(v0);
    __nv_bfloat16 h1 = __float2bfloat16_rn(v1);
    __nv_bfloat16 l0 = __float2bfloat16_rn(v0 - __bfloat162float(h0));
    __nv_bfloat16 l1 = __float2bfloat16_rn(v1 - __bfloat162float(h1));
    __nv_bfloat162 hp = __nv_bfloat162(h0, h1), lp = __nv_bfloat162(l0, l1);
    hi = *(uint32_t*)&hp;
    lo = *(uint32_t*)&lp;
}

__device__ __forceinline__ void hmma(float* d, const uint32_t* a, uint32_t b0, uint32_t b1) {
    asm volatile(
        "mma.sync.aligned.m16n8k16.row.col.f32.bf16.bf16.f32 "
        "{%0,%1,%2,%3}, {%4,%5,%6,%7}, {%8,%9}, {%0,%1,%2,%3};"
        : "+f"(d[0]), "+f"(d[1]), "+f"(d[2]), "+f"(d[3])
        : "r"(a[0]), "r"(a[1]), "r"(a[2]), "r"(a[3]), "r"(b0), "r"(b1));
}

__global__ void __launch_bounds__(256) out_mma(const float* __restrict__ x,
                                               const float* __restrict__ ner,
                                               const float* __restrict__ nei,
                                               const float* __restrict__ bre,
                                               const float* __restrict__ bim,
                                               float* __restrict__ out) {
    extern __shared__ char smc[];
    uint32_t* wh = (uint32_t*)(smc + SM_WH);
    uint32_t* wl = (uint32_t*)(smc + SM_WL);
    uint32_t* xh = (uint32_t*)(smc + SM_XH);
    uint32_t* xl = (uint32_t*)(smc + SM_XL);
    float* bias = (float*)(smc + SM_BIAS);

    int tid = threadIdx.x;
    int wid = tid >> 5, lane = tid & 31;
    int oh = blockIdx.x;
    int v = blockIdx.y;

    // ---- fill W half ----
    {
        const float4* ac = g_AC4 + (size_t)v * 4096 + oh * 32;
#pragma unroll
        for (int it = 0; it < 4; it++) {
            int idx = tid + it * 256;
            int p = idx >> 5;
            int ol = idx & 31;
            int i0 = p * 2;
            float4 c0 = ac[i0 * 64 + ol];
            float4 c1 = ac[(i0 + 1) * 64 + ol];
            uint32_t r0 = (2 * ol) * SW + p;
            uint32_t r1 = (2 * ol + 1) * SW + p;
            uint32_t hi, lo;
            split_pack(c0.x, c1.x, hi, lo);   wh[r0]      = hi; wl[r0]      = lo;
            split_pack(c0.z, c1.z, hi, lo);   wh[r0 + 32] = hi; wl[r0 + 32] = lo;
            split_pack(-c0.w, -c1.w, hi, lo); wh[r0 + 64] = hi; wl[r0 + 64] = lo;
            split_pack(c0.y, c1.y, hi, lo);   wh[r1]      = hi; wl[r1]      = lo;
            split_pack(c0.w, c1.w, hi, lo);   wh[r1 + 32] = hi; wl[r1 + 32] = lo;
            split_pack(c0.z, c1.z, hi, lo);   wh[r1 + 64] = hi; wl[r1 + 64] = lo;
        }
    }
    // ---- fill X ----
#pragma unroll
    for (int it = 0; it < 8; it++) {
        int idx = tid + it * 256;
        int b = idx >> 5;
        int p = idx & 31;
        int i0 = p * 2;
        size_t go = ((size_t)b * VV + v) * 64 + i0;
        float2 xv = *(const float2*)&x[go];
        float4 yv = *(const float4*)&g_y[go];
        uint32_t r = b * SW + p;
        uint32_t hi, lo;
        split_pack(xv.x, xv.y, hi, lo); xh[r]      = hi; xl[r]      = lo;
        split_pack(yv.x, yv.z, hi, lo); xh[r + 32] = hi; xl[r + 32] = lo;
        split_pack(yv.y, yv.w, hi, lo); xh[r + 64] = hi; xl[r + 64] = lo;
    }
    // ---- bias ----
    if (tid < 64) {
        int ol = tid >> 1, rei = tid & 1;
        int o = oh * 32 + ol;
        float re = 0.f, im = 0.f;
#pragma unroll
        for (int d = 0; d < 16; d++) {
            float a = ner[v * 16 + d], b2 = nei[v * 16 + d];
            float pr = bre[d * 64 + o], pi = bim[d * 64 + o];
            re += a * pr - b2 * pi;
            im += a * pi + b2 * pr;
        }
        bias[tid] = rei ? im : re;
    }
    __syncthreads();

    // ---- compute: warp (mt, nh) = 16 m x 32 n; 3 independent acc sets ----
    int gid = lane >> 2, tig = lane & 3;
    int mt = wid & 3, nh = wid >> 2;
    int m0 = mt * 16;
    float accH[4][4] = {}, accL[4][4] = {}, accM[4][4] = {};

    for (int kc = 0; kc < 12; kc++) {
        int ka = kc * 8 + tig;
        uint32_t ah[4], al[4];
        int rlo = (m0 + gid) * SW + ka;
        int rhi = rlo + 8 * SW;
        ah[0] = wh[rlo];     ah[1] = wh[rhi];
        ah[2] = wh[rlo + 4]; ah[3] = wh[rhi + 4];
        al[0] = wl[rlo];     al[1] = wl[rhi];
        al[2] = wl[rlo + 4]; al[3] = wl[rhi + 4];
#pragma unroll
        for (int nt = 0; nt < 4; nt++) {
            int rb = (nh * 32 + nt * 8 + gid) * SW + ka;
            uint32_t bh0 = xh[rb], bh1 = xh[rb + 4];
            uint32_t bl0 = xl[rb], bl1 = xl[rb + 4];
            hmma(accH[nt], ah, bh0, bh1);
            hmma(accL[nt], al, bh0, bh1);
            hmma(accM[nt], ah, bl0, bl1);
        }
    }

    // ---- epilogue: merge passes, add bias, store ----
    int m_lo = m0 + gid, m_hi = m0 + gid + 8;
    float b_lo = bias[m_lo], b_hi = bias[m_hi];
    int ng_lo = oh * 64 + m_lo, ng_hi = oh * 64 + m_hi;
#pragma unroll
    for (int nt = 0; nt < 4; nt++) {
        int b0 = nh * 32 + nt * 8 + 2 * tig;
        size_t o00 = ((size_t)b0 * VV + v) * 128;
        size_t o01 = ((size_t)(b0 + 1) * VV + v) * 128;
        out[o00 + ng_lo] = accH[nt][0] + accL[nt][0] + accM[nt][0] + b_lo;
        out[o01 + ng_lo] = accH[nt][1] + accL[nt][1] + accM[nt][1] + b_lo;
        out[o00 + ng_hi] = accH[nt][2] + accL[nt][2] + accM[nt][2] + b_hi;
        out[o01 + ng_hi] = accH[nt][3] + accL[nt][3] + accM[nt][3] + b_hi;
    }
}

extern "C" void kernel_launch(void* const* d_in, const int* in_sizes, int n_in,
                              void* d_out, int out_size) {
    const float* x   = (const float*)d_in[0];
    const float* ner = (const float*)d_in[1];
    const float* nei = (const float*)d_in[2];
    const float* wr  = (const float*)d_in[3];
    const float* wi  = (const float*)d_in[4];
    const float* bre = (const float*)d_in[5];
    const float* bim = (const float*)d_in[6];
    float* out = (float*)d_out;

    cudaFuncSetAttribute(out_mma, cudaFuncAttributeMaxDynamicSharedMemorySize, SM_TOTAL);

    k1_gram_z<<<32 + 2 * BB, 256>>>(x, ner, nei);             // L1
    k2_reduce_y<<<1 + BB * 32, 256>>>(ner, nei);              // L2
    wcomb_kernel<<<dim3(8, 56), 256>>>(ner, nei, wr, wi);     // L3
    out_mma<<<dim3(2, VV), 256, SM_TOTAL>>>(x, ner, nei, bre, bim, out);  // L4 (ncu target)
}